// round 2
// baseline (speedup 1.0000x reference)
#include <cuda_runtime.h>

#define NB    4
#define CDIM  512
#define NHEAD 8
#define HD    64
#define NSP   4096            // H*W = 64*64
#define NBH   (NB*NHEAD)      // 32

// Scratch (device globals; no allocations allowed).
// Layout for q/k/v: [bh][d][n]  (n contiguous)  -> attention loads Q/K tiles with no transpose.
// Layout for o:     [b][c][n]   (c = h*64+d)    -> feeds out-proj GEMM directly.
__device__ float g_q[NBH * HD * NSP];
__device__ float g_k[NBH * HD * NSP];
__device__ float g_v[NBH * HD * NSP];
__device__ float g_o[NB * CDIM * NSP];

// ---------------------------------------------------------------------------
// Tiled GEMM: C[b][o][n] = sum_c W[o][c] * In[b][c][n]
// MODE 0: QKV projection  (M=1536), epilogue splits into g_q/g_k/g_v [bh][d][n]
// MODE 1: output projection (M=512), reads g_o, writes d_out [b][c][n]
// Tile 64x64, K-tile 16, 256 threads, 4x4 microtile per thread.
// ---------------------------------------------------------------------------
template <int MODE>
__global__ void __launch_bounds__(256) gemm_kernel(const float* __restrict__ In,
                                                   const float* __restrict__ W,
                                                   float* __restrict__ Out) {
    __shared__ float As[16 * 65];   // [k][o], stride 65 (write-conflict relief)
    __shared__ float Bs[16 * 64];   // [k][n]

    const int t  = threadIdx.x;
    const int n0 = (t & 15) * 4;    // float4 dim (n)
    const int o0 = (t >> 4) * 4;

    float acc[4][4];
#pragma unroll
    for (int i = 0; i < 4; i++)
#pragma unroll
        for (int j = 0; j < 4; j++) acc[i][j] = 0.0f;

    const float* src = (MODE == 0) ? In : g_o;
    const float* Wt  = W + (size_t)(blockIdx.y * 64) * CDIM;
    const float* Xt  = src + (size_t)blockIdx.z * CDIM * NSP + blockIdx.x * 64;

    const int ar = t >> 2;          // A tile row (o), 64 rows x 4 threads
    const int ac = (t & 3) * 4;     // A tile col base (k)
    const int br = t >> 4;          // B tile row (k), 16 rows x 16 threads
    const int bc = (t & 15) * 4;    // B tile col base (n)

    for (int kt = 0; kt < CDIM; kt += 16) {
        float4 a = *(const float4*)&Wt[(size_t)ar * CDIM + kt + ac];
        As[(ac + 0) * 65 + ar] = a.x;
        As[(ac + 1) * 65 + ar] = a.y;
        As[(ac + 2) * 65 + ar] = a.z;
        As[(ac + 3) * 65 + ar] = a.w;
        *(float4*)&Bs[br * 64 + bc] =
            *(const float4*)&Xt[(size_t)(kt + br) * NSP + bc];
        __syncthreads();
#pragma unroll
        for (int kk = 0; kk < 16; kk++) {
            float4 b4 = *(float4*)&Bs[kk * 64 + n0];
            float ba[4] = {b4.x, b4.y, b4.z, b4.w};
            float aa[4];
#pragma unroll
            for (int i = 0; i < 4; i++) aa[i] = As[kk * 65 + o0 + i];
#pragma unroll
            for (int i = 0; i < 4; i++)
#pragma unroll
                for (int j = 0; j < 4; j++) acc[i][j] += aa[i] * ba[j];
        }
        __syncthreads();
    }

    const int n = blockIdx.x * 64 + n0;
    if (MODE == 0) {
        const int s = blockIdx.y >> 3;       // 0=q 1=k 2=v
        const int h = blockIdx.y & 7;
        const int b = blockIdx.z;
        float* dst = (s == 0) ? g_q : (s == 1) ? g_k : g_v;
        const size_t base = (size_t)(b * NHEAD + h) * HD * NSP;
#pragma unroll
        for (int i = 0; i < 4; i++) {
            *(float4*)&dst[base + (size_t)(o0 + i) * NSP + n] =
                make_float4(acc[i][0], acc[i][1], acc[i][2], acc[i][3]);
        }
    } else {
        const size_t base = ((size_t)blockIdx.z * CDIM + blockIdx.y * 64) * NSP;
#pragma unroll
        for (int i = 0; i < 4; i++) {
            *(float4*)&Out[base + (size_t)(o0 + i) * NSP + n] =
                make_float4(acc[i][0], acc[i][1], acc[i][2], acc[i][3]);
        }
    }
}

// ---------------------------------------------------------------------------
// RoPE on q and k, in place. Layout [bh][d][n]; pair (d, d+32).
// cos/sin: j<16 -> angle = ph * 10000^(-j/16); j>=16 -> pw * 10000^(-(j-16)/16)
// ---------------------------------------------------------------------------
__global__ void __launch_bounds__(256) rope_kernel() {
    const int idx = blockIdx.x * 256 + threadIdx.x;   // [bh][j][n]
    const int n   = idx & (NSP - 1);
    const int j   = (idx >> 12) & 31;
    const int bh  = idx >> 17;

    const int ph = n >> 6;
    const int pw = n & 63;
    const float jf  = (float)(j < 16 ? j : j - 16);
    const float pos = (float)(j < 16 ? ph : pw);
    // 10000^(-jf/16) = 2^(-jf * log2(10000)/16)
    const float freq = exp2f(-0.8304820237218406f * jf);
    const float ang  = pos * freq;
    float sn, cs;
    sincosf(ang, &sn, &cs);

    const size_t b0 = (size_t)bh * HD * NSP + n;
    const size_t i1 = b0 + (size_t)j * NSP;
    const size_t i2 = b0 + (size_t)(j + 32) * NSP;

    float q1 = g_q[i1], q2 = g_q[i2];
    g_q[i1] = q1 * cs - q2 * sn;
    g_q[i2] = q1 * sn + q2 * cs;
    float k1 = g_k[i1], k2 = g_k[i2];
    g_k[i1] = k1 * cs - k2 * sn;
    g_k[i2] = k1 * sn + k2 * cs;
}

// ---------------------------------------------------------------------------
// Flash attention, fp32 SIMT. One block = one (bh, 64-row q tile).
// Smem: Qs[d][r], Ks[d][c] (direct copies, [d][n] global layout), Vs[c][d]
// (transposed on load), Pt[c][r] stride 65. Online softmax per row.
// ---------------------------------------------------------------------------
#define ATTN_SMEM ((3 * 64 * 64 + 64 * 65 + 3 * 64) * 4)

__global__ void __launch_bounds__(256) attn_kernel() {
    extern __shared__ float sm[];
    float* Qs  = sm;                   // 4096: [d][r]
    float* Ks  = sm + 4096;            // 4096: [d][c]
    float* Vs  = sm + 8192;            // 4096: [c][d]
    float* Pt  = sm + 12288;           // 64*65: [c][r]
    float* msm = sm + 12288 + 4160;    // 64
    float* lsm = msm + 64;             // 64
    float* csm = lsm + 64;             // 64

    const int t     = threadIdx.x;
    const int bh    = blockIdx.y;
    const int ntile = blockIdx.x * 64;

    const size_t off = (size_t)bh * HD * NSP;
    const float* Qg = g_q + off + ntile;
    const float* Kg = g_k + off;
    const float* Vg = g_v + off;

    const int lr = t >> 2;          // load row (d for Q/K/V), 0..63
    const int lc = (t & 3) * 16;    // load col segment base

    // Q tile (scaled by hd^-1/2 = 0.125), direct copy [d][r]
#pragma unroll
    for (int k = 0; k < 4; k++) {
        float4 v = *(const float4*)&Qg[(size_t)lr * NSP + lc + k * 4];
        v.x *= 0.125f; v.y *= 0.125f; v.z *= 0.125f; v.w *= 0.125f;
        *(float4*)&Qs[lr * 64 + lc + k * 4] = v;
    }
    if (t < 64) { msm[t] = -1e30f; lsm[t] = 0.0f; }

    float o[4][4];
#pragma unroll
    for (int i = 0; i < 4; i++)
#pragma unroll
        for (int j = 0; j < 4; j++) o[i][j] = 0.0f;

    const int r0 = (t >> 4) * 4;    // row (n) microtile base
    const int c0 = (t & 15) * 4;    // col microtile base (c in S phase, d in PV)

    for (int kt = 0; kt < 64; kt++) {
        const float* Kt = Kg + kt * 64;
        const float* Vt = Vg + kt * 64;
        // K: direct copy [d][c]
#pragma unroll
        for (int k = 0; k < 4; k++) {
            *(float4*)&Ks[lr * 64 + lc + k * 4] =
                *(const float4*)&Kt[(size_t)lr * NSP + lc + k * 4];
        }
        // V: transpose to [c][d]
#pragma unroll
        for (int k = 0; k < 4; k++) {
            float4 v = *(const float4*)&Vt[(size_t)lr * NSP + lc + k * 4];
            const int c = lc + k * 4;
            Vs[(c + 0) * 64 + lr] = v.x;
            Vs[(c + 1) * 64 + lr] = v.y;
            Vs[(c + 2) * 64 + lr] = v.z;
            Vs[(c + 3) * 64 + lr] = v.w;
        }
        __syncthreads();

        // ---- S = (Q*scale) K^T ----
        float s[4][4];
#pragma unroll
        for (int i = 0; i < 4; i++)
#pragma unroll
            for (int j = 0; j < 4; j++) s[i][j] = 0.0f;
#pragma unroll 8
        for (int d = 0; d < 64; d++) {
            float4 q4 = *(float4*)&Qs[d * 64 + r0];
            float4 k4 = *(float4*)&Ks[d * 64 + c0];
            float qa[4] = {q4.x, q4.y, q4.z, q4.w};
            float ka[4] = {k4.x, k4.y, k4.z, k4.w};
#pragma unroll
            for (int i = 0; i < 4; i++)
#pragma unroll
                for (int j = 0; j < 4; j++) s[i][j] += qa[i] * ka[j];
        }
#pragma unroll
        for (int i = 0; i < 4; i++)
#pragma unroll
            for (int j = 0; j < 4; j++)
                Pt[(c0 + j) * 65 + (r0 + i)] = s[i][j];
        __syncthreads();

        // ---- online softmax (4 threads per row) ----
        {
            const int r   = t >> 2;
            const int seg = (t & 3) * 16;
            float mx = -1e30f;
#pragma unroll
            for (int cc = 0; cc < 16; cc++)
                mx = fmaxf(mx, Pt[(seg + cc) * 65 + r]);
            mx = fmaxf(mx, __shfl_xor_sync(0xffffffffu, mx, 1));
            mx = fmaxf(mx, __shfl_xor_sync(0xffffffffu, mx, 2));
            const float mold = msm[r];
            const float mnew = fmaxf(mold, mx);
            float sum = 0.0f;
#pragma unroll
            for (int cc = 0; cc < 16; cc++) {
                const int pidx = (seg + cc) * 65 + r;
                float p = __expf(Pt[pidx] - mnew);
                Pt[pidx] = p;
                sum += p;
            }
            sum += __shfl_xor_sync(0xffffffffu, sum, 1);
            sum += __shfl_xor_sync(0xffffffffu, sum, 2);
            if ((t & 3) == 0) {
                const float corr = __expf(mold - mnew);
                msm[r] = mnew;
                lsm[r] = lsm[r] * corr + sum;
                csm[r] = corr;
            }
        }
        __syncthreads();

        // ---- O = O*corr + P V ----
        {
            float cf[4];
#pragma unroll
            for (int i = 0; i < 4; i++) cf[i] = csm[r0 + i];
#pragma unroll
            for (int i = 0; i < 4; i++)
#pragma unroll
                for (int j = 0; j < 4; j++) o[i][j] *= cf[i];
        }
#pragma unroll 4
        for (int c = 0; c < 64; c++) {
            float4 v4 = *(float4*)&Vs[c * 64 + c0];
            float va[4] = {v4.x, v4.y, v4.z, v4.w};
#pragma unroll
            for (int i = 0; i < 4; i++) {
                const float p = Pt[c * 65 + r0 + i];
#pragma unroll
                for (int j = 0; j < 4; j++) o[i][j] += p * va[j];
            }
        }
        __syncthreads();
    }

    // finalize: divide by l, store transposed to g_o[b][c][n]
    float inv[4];
#pragma unroll
    for (int i = 0; i < 4; i++) inv[i] = 1.0f / lsm[r0 + i];
#pragma unroll
    for (int j = 0; j < 4; j++) {
        float4 val = make_float4(o[0][j] * inv[0], o[1][j] * inv[1],
                                 o[2][j] * inv[2], o[3][j] * inv[3]);
        *(float4*)&g_o[((size_t)bh * HD + c0 + j) * NSP + ntile + r0] = val;
    }
}

// ---------------------------------------------------------------------------
extern "C" void kernel_launch(void* const* d_in, const int* in_sizes, int n_in,
                              void* d_out, int out_size) {
    const float* x      = (const float*)d_in[0];
    const float* w_qkv  = (const float*)d_in[1];
    const float* w_proj = (const float*)d_in[2];
    float* out = (float*)d_out;

    cudaFuncSetAttribute(attn_kernel,
                         cudaFuncAttributeMaxDynamicSharedMemorySize, ATTN_SMEM);

    // 1) QKV projection: M=1536 -> 24 o-tiles
    gemm_kernel<0><<<dim3(NSP / 64, 24, NB), 256>>>(x, w_qkv, nullptr);
    // 2) RoPE on q, k
    rope_kernel<<<(NBH * 32 * NSP) / 256, 256>>>();
    // 3) attention
    attn_kernel<<<dim3(NSP / 64, NBH), 256, ATTN_SMEM>>>();
    // 4) output projection: M=512 -> 8 o-tiles
    gemm_kernel<1><<<dim3(NSP / 64, 8, NB), 256>>>(nullptr, w_proj, out);
}

// round 4
// speedup vs baseline: 1.1379x; 1.1379x over previous
#include <cuda_runtime.h>

#define NB    4
#define CDIM  512
#define NHEAD 8
#define HD    64
#define NSP   4096
#define NBH   (NB*NHEAD)

typedef unsigned long long ull;

__device__ float g_q[NBH * HD * NSP];
__device__ float g_k[NBH * HD * NSP];
__device__ float g_v[NBH * HD * NSP];
__device__ float g_o[NB * CDIM * NSP];

// ---- packed f32x2 helpers (Blackwell FFMA2 path, PTX-only) ----
__device__ __forceinline__ ull pk2(float lo, float hi) {
    ull r; asm("mov.b64 %0,{%1,%2};" : "=l"(r) : "f"(lo), "f"(hi)); return r;
}
__device__ __forceinline__ void upk2(ull v, float& lo, float& hi) {
    asm("mov.b64 {%0,%1},%2;" : "=f"(lo), "=f"(hi) : "l"(v));
}
__device__ __forceinline__ ull ffma2(ull a, ull b, ull c) {
    ull r; asm("fma.rn.f32x2 %0,%1,%2,%3;" : "=l"(r) : "l"(a), "l"(b), "l"(c)); return r;
}
__device__ __forceinline__ ull fmul2(ull a, ull b) {
    ull r; asm("mul.rn.f32x2 %0,%1,%2;" : "=l"(r) : "l"(a), "l"(b)); return r;
}

// ---------------------------------------------------------------------------
// GEMM: C[b][o][n] = sum_c W[o][c] * In[b][c][n]
// 128x128 tile, K-tile 16, 256 threads, 8x8 microtile (pairs packed along n).
// MODE 0: QKV (M=1536) -> split into g_q/g_k/g_v [bh][d][n]
// MODE 1: out-proj (M=512), reads g_o, writes d_out
// ---------------------------------------------------------------------------
template <int MODE>
__global__ void __launch_bounds__(256) gemm_kernel(const float* __restrict__ In,
                                                   const float* __restrict__ W,
                                                   float* __restrict__ Out) {
    __shared__ float As[16 * 132];   // [k][o]
    __shared__ float Bs[16 * 132];   // [k][n]

    const int t = threadIdx.x;
    const float* src = (MODE == 0) ? In : g_o;
    const float* Wt  = W + (size_t)(blockIdx.y * 128) * CDIM;
    const float* Xt  = src + (size_t)blockIdx.z * CDIM * NSP + blockIdx.x * 128;

    const int wr = t >> 1;           // W row (o), 128 rows x 2 threads
    const int wc = (t & 1) * 8;      // W col base (k)
    const int br = t >> 4;           // B row (k)
    const int bc = (t & 15) * 8;     // B col base (n)
    const int o0 = (t >> 4) * 8;
    const int n0 = (t & 15) * 8;

    ull acc[8][4];
#pragma unroll
    for (int i = 0; i < 8; i++)
#pragma unroll
        for (int m = 0; m < 4; m++) acc[i][m] = 0ULL;

    for (int kt = 0; kt < CDIM; kt += 16) {
        float4 w0 = *(const float4*)&Wt[(size_t)wr * CDIM + kt + wc];
        float4 w1 = *(const float4*)&Wt[(size_t)wr * CDIM + kt + wc + 4];
        As[(wc + 0) * 132 + wr] = w0.x;
        As[(wc + 1) * 132 + wr] = w0.y;
        As[(wc + 2) * 132 + wr] = w0.z;
        As[(wc + 3) * 132 + wr] = w0.w;
        As[(wc + 4) * 132 + wr] = w1.x;
        As[(wc + 5) * 132 + wr] = w1.y;
        As[(wc + 6) * 132 + wr] = w1.z;
        As[(wc + 7) * 132 + wr] = w1.w;
        *(float4*)&Bs[br * 132 + bc] =
            *(const float4*)&Xt[(size_t)(kt + br) * NSP + bc];
        *(float4*)&Bs[br * 132 + bc + 4] =
            *(const float4*)&Xt[(size_t)(kt + br) * NSP + bc + 4];
        __syncthreads();
#pragma unroll
        for (int kk = 0; kk < 16; kk++) {
            float4 a0 = *(float4*)&As[kk * 132 + o0];
            float4 a1 = *(float4*)&As[kk * 132 + o0 + 4];
            const ull* bp = (const ull*)&Bs[kk * 132 + n0];
            ull b0 = bp[0], b1 = bp[1], b2 = bp[2], b3 = bp[3];
            float av[8] = {a0.x, a0.y, a0.z, a0.w, a1.x, a1.y, a1.z, a1.w};
#pragma unroll
            for (int i = 0; i < 8; i++) {
                ull ai = pk2(av[i], av[i]);
                acc[i][0] = ffma2(ai, b0, acc[i][0]);
                acc[i][1] = ffma2(ai, b1, acc[i][1]);
                acc[i][2] = ffma2(ai, b2, acc[i][2]);
                acc[i][3] = ffma2(ai, b3, acc[i][3]);
            }
        }
        __syncthreads();
    }

    const int n = blockIdx.x * 128 + n0;
#pragma unroll
    for (int i = 0; i < 8; i++) {
        float* dst;
        size_t row;
        if (MODE == 0) {
            const int oo = blockIdx.y * 128 + o0 + i;
            const int s  = oo >> 9;
            const int h  = (oo >> 6) & 7;
            const int d  = oo & 63;
            dst = (s == 0) ? g_q : (s == 1) ? g_k : g_v;
            row = ((size_t)(blockIdx.z * NHEAD + h) * HD + d);
        } else {
            dst = Out;
            row = (size_t)blockIdx.z * CDIM + blockIdx.y * 128 + o0 + i;
        }
#pragma unroll
        for (int m = 0; m < 4; m++) {
            float lo, hi; upk2(acc[i][m], lo, hi);
            *(float2*)&dst[row * NSP + n + 2 * m] = make_float2(lo, hi);
        }
    }
}

// ---------------------------------------------------------------------------
// RoPE on q and k in place. Layout [bh][d][n]; pair (d, d+32).
// ---------------------------------------------------------------------------
__global__ void __launch_bounds__(256) rope_kernel() {
    const int idx = blockIdx.x * 256 + threadIdx.x;
    const int n   = idx & (NSP - 1);
    const int j   = (idx >> 12) & 31;
    const int bh  = idx >> 17;

    const int ph = n >> 6;
    const int pw = n & 63;
    const float jf  = (float)(j < 16 ? j : j - 16);
    const float pos = (float)(j < 16 ? ph : pw);
    const float freq = exp2f(-0.8304820237218406f * jf);
    const float ang  = pos * freq;
    float sn, cs;
    sincosf(ang, &sn, &cs);

    const size_t b0 = (size_t)bh * HD * NSP + n;
    const size_t i1 = b0 + (size_t)j * NSP;
    const size_t i2 = b0 + (size_t)(j + 32) * NSP;

    float q1 = g_q[i1], q2 = g_q[i2];
    g_q[i1] = q1 * cs - q2 * sn;
    g_q[i2] = q1 * sn + q2 * cs;
    float k1 = g_k[i1], k2 = g_k[i2];
    g_k[i1] = k1 * cs - k2 * sn;
    g_k[i2] = k1 * sn + k2 * cs;
}

// ---------------------------------------------------------------------------
// Flash attention fp32 + f32x2. BR=128, BC=128, 256 threads.
// Smem: Qs[d][r] 64x128, Ks[d][c] 64x128, Vs[c][d] 128x68(pad),
//       Pt[c][r-swizzled] 128x128, stats 3x128.
// S microtile 8r x 8c (acc packed along r-pairs); PV microtile 8r x 4d.
// ---------------------------------------------------------------------------
#define QS_OFF   0
#define KS_OFF   8192
#define VS_OFF   16384
#define PT_BASE  25088           // 16384 + 8704
#define ST_OFF   41472
#define ATTN_SMEM ((41472 + 384) * 4)

#define PIDX(c, r) ((c) * 128 + ((r) ^ ((((c) >> 3) & 7) << 2)))

__global__ void __launch_bounds__(256) attn_kernel() {
    extern __shared__ float sm[];
    float* Qs  = sm + QS_OFF;
    float* Ks  = sm + KS_OFF;
    float* Vs  = sm + VS_OFF;
    float* Pt  = sm + PT_BASE;
    float* msm = sm + ST_OFF;
    float* lsm = msm + 128;
    float* csm = lsm + 128;

    const int t     = threadIdx.x;
    const int bh    = blockIdx.y;
    const int ntile = blockIdx.x * 128;

    const size_t off = (size_t)bh * HD * NSP;
    const float* Qg = g_q + off + ntile;
    const float* Kg = g_k + off;
    const float* Vg = g_v + off;

    const int lr = t >> 2;           // 0..63 (d)
    const int lc = (t & 3) * 32;     // col segment base

    // Q tile [d][r], scaled by hd^-1/2
#pragma unroll
    for (int k = 0; k < 8; k++) {
        float4 v = *(const float4*)&Qg[(size_t)lr * NSP + lc + k * 4];
        v.x *= 0.125f; v.y *= 0.125f; v.z *= 0.125f; v.w *= 0.125f;
        *(float4*)&Qs[lr * 128 + lc + k * 4] = v;
    }
    if (t < 128) { msm[t] = -1e30f; lsm[t] = 0.0f; }

    const int r0 = (t >> 4) * 8;     // row microtile base (8 rows)
    const int c0 = (t & 15) * 8;     // col microtile base (S phase)
    const int d0 = (t & 15) * 4;     // d microtile base (PV phase)

    ull o2[4][4];                    // [r-pair][d]  rows (r0+2i, r0+2i+1)
#pragma unroll
    for (int i = 0; i < 4; i++)
#pragma unroll
        for (int m = 0; m < 4; m++) o2[i][m] = 0ULL;

    for (int kt = 0; kt < 32; kt++) {
        const float* Kt = Kg + kt * 128;
        const float* Vt = Vg + kt * 128;
#pragma unroll
        for (int k = 0; k < 8; k++) {
            *(float4*)&Ks[lr * 128 + lc + k * 4] =
                *(const float4*)&Kt[(size_t)lr * NSP + lc + k * 4];
        }
#pragma unroll
        for (int k = 0; k < 8; k++) {
            float4 v = *(const float4*)&Vt[(size_t)lr * NSP + lc + k * 4];
            const int c = lc + k * 4;
            Vs[(c + 0) * 68 + lr] = v.x;
            Vs[(c + 1) * 68 + lr] = v.y;
            Vs[(c + 2) * 68 + lr] = v.z;
            Vs[(c + 3) * 68 + lr] = v.w;
        }
        __syncthreads();

        // ---- S = (Q*scale)^T-tile K: acc packed along r-pairs ----
        ull s2[4][8];
#pragma unroll
        for (int i = 0; i < 4; i++)
#pragma unroll
            for (int j = 0; j < 8; j++) s2[i][j] = 0ULL;
#pragma unroll 4
        for (int d = 0; d < 64; d++) {
            const ull* qp = (const ull*)&Qs[d * 128 + r0];
            ull q0 = qp[0], q1 = qp[1], q2 = qp[2], q3 = qp[3];
            float4 ka = *(float4*)&Ks[d * 128 + c0];
            float4 kb = *(float4*)&Ks[d * 128 + c0 + 4];
            float kv[8] = {ka.x, ka.y, ka.z, ka.w, kb.x, kb.y, kb.z, kb.w};
#pragma unroll
            for (int j = 0; j < 8; j++) {
                ull kj = pk2(kv[j], kv[j]);
                s2[0][j] = ffma2(q0, kj, s2[0][j]);
                s2[1][j] = ffma2(q1, kj, s2[1][j]);
                s2[2][j] = ffma2(q2, kj, s2[2][j]);
                s2[3][j] = ffma2(q3, kj, s2[3][j]);
            }
        }
        // store transposed to Pt[c][r] as b64 pairs (rows contiguous)
#pragma unroll
        for (int i = 0; i < 4; i++)
#pragma unroll
            for (int j = 0; j < 8; j++)
                *(ull*)&Pt[PIDX(c0 + j, r0 + 2 * i)] = s2[i][j];
        __syncthreads();

        // ---- online softmax: 2 threads per row ----
        {
            const int r   = t >> 1;
            const int seg = (t & 1) * 64;
            float mx = -1e30f;
#pragma unroll 8
            for (int cc = 0; cc < 64; cc++)
                mx = fmaxf(mx, Pt[PIDX(seg + cc, r)]);
            mx = fmaxf(mx, __shfl_xor_sync(0xffffffffu, mx, 1));
            const float mold = msm[r];
            const float mnew = fmaxf(mold, mx);
            float sum = 0.0f;
#pragma unroll 8
            for (int cc = 0; cc < 64; cc++) {
                const int pidx = PIDX(seg + cc, r);
                float p = __expf(Pt[pidx] - mnew);
                Pt[pidx] = p;
                sum += p;
            }
            sum += __shfl_xor_sync(0xffffffffu, sum, 1);
            if ((t & 1) == 0) {
                const float corr = __expf(mold - mnew);
                msm[r] = mnew;
                lsm[r] = lsm[r] * corr + sum;
                csm[r] = corr;
            }
        }
        __syncthreads();

        // ---- O = O*corr + P V ----
#pragma unroll
        for (int i = 0; i < 4; i++) {
            ull cf = pk2(csm[r0 + 2 * i], csm[r0 + 2 * i + 1]);
#pragma unroll
            for (int m = 0; m < 4; m++) o2[i][m] = fmul2(o2[i][m], cf);
        }
#pragma unroll 2
        for (int c = 0; c < 128; c++) {
            const ull* ppa = (const ull*)&Pt[PIDX(c, r0)];
            const ull* ppb = (const ull*)&Pt[PIDX(c, r0 + 4)];
            ull p0 = ppa[0], p1 = ppa[1], p2v = ppb[0], p3 = ppb[1];
            float4 va = *(float4*)&Vs[c * 68 + d0];
            float vv[4] = {va.x, va.y, va.z, va.w};
#pragma unroll
            for (int m = 0; m < 4; m++) {
                ull vm = pk2(vv[m], vv[m]);
                o2[0][m] = ffma2(p0, vm, o2[0][m]);
                o2[1][m] = ffma2(p1, vm, o2[1][m]);
                o2[2][m] = ffma2(p2v, vm, o2[2][m]);
                o2[3][m] = ffma2(p3, vm, o2[3][m]);
            }
        }
        __syncthreads();
    }

    // finalize: divide by l, store to g_o[b][c][n] (n-pairs contiguous)
#pragma unroll
    for (int i = 0; i < 4; i++) {
        ull iv = pk2(1.0f / lsm[r0 + 2 * i], 1.0f / lsm[r0 + 2 * i + 1]);
#pragma unroll
        for (int m = 0; m < 4; m++) {
            ull v = fmul2(o2[i][m], iv);
            float lo, hi; upk2(v, lo, hi);
            *(float2*)&g_o[((size_t)bh * HD + d0 + m) * NSP + ntile + r0 + 2 * i] =
                make_float2(lo, hi);
        }
    }
}

// ---------------------------------------------------------------------------
extern "C" void kernel_launch(void* const* d_in, const int* in_sizes, int n_in,
                              void* d_out, int out_size) {
    const float* x      = (const float*)d_in[0];
    const float* w_qkv  = (const float*)d_in[1];
    const float* w_proj = (const float*)d_in[2];
    float* out = (float*)d_out;

    cudaFuncSetAttribute(attn_kernel,
                         cudaFuncAttributeMaxDynamicSharedMemorySize, ATTN_SMEM);

    gemm_kernel<0><<<dim3(NSP / 128, 12, NB), 256>>>(x, w_qkv, nullptr);
    rope_kernel<<<(NBH * 32 * NSP) / 256, 256>>>();
    attn_kernel<<<dim3(NSP / 128, NBH), 256, ATTN_SMEM>>>();
    gemm_kernel<1><<<dim3(NSP / 128, 4, NB), 256>>>(nullptr, w_proj, out);
}

// round 5
// speedup vs baseline: 2.1688x; 1.9060x over previous
#include <cuda_runtime.h>

#define NB    4
#define CDIM  512
#define NHEAD 8
#define HD    64
#define NSP   4096
#define NBH   (NB*NHEAD)

typedef unsigned long long ull;

// q,k: [bh][n][d]   v: [bh][d][n]   o: [b][c][n]
__device__ float g_q[NBH * NSP * HD];
__device__ float g_k[NBH * NSP * HD];
__device__ float g_v[NBH * HD * NSP];
__device__ float g_o[NB * CDIM * NSP];

// ---- packed f32x2 helpers ----
__device__ __forceinline__ ull pk2(float lo, float hi) {
    ull r; asm("mov.b64 %0,{%1,%2};" : "=l"(r) : "f"(lo), "f"(hi)); return r;
}
__device__ __forceinline__ void upk2(ull v, float& lo, float& hi) {
    asm("mov.b64 {%0,%1},%2;" : "=f"(lo), "=f"(hi) : "l"(v));
}
__device__ __forceinline__ ull ffma2(ull a, ull b, ull c) {
    ull r; asm("fma.rn.f32x2 %0,%1,%2,%3;" : "=l"(r) : "l"(a), "l"(b), "l"(c)); return r;
}

// ---- tf32 mma helpers ----
__device__ __forceinline__ unsigned cvt_tf32(float f) {
    unsigned r; asm("cvt.rna.tf32.f32 %0,%1;" : "=r"(r) : "f"(f)); return r;
}
__device__ __forceinline__ float ex2(float x) {
    float r; asm("ex2.approx.f32 %0,%1;" : "=f"(r) : "f"(x)); return r;
}
__device__ __forceinline__ void mma8(float4& d, unsigned a0, unsigned a1,
                                     unsigned a2, unsigned a3,
                                     unsigned b0, unsigned b1) {
    asm("mma.sync.aligned.m16n8k8.row.col.f32.tf32.tf32.f32 "
        "{%0,%1,%2,%3},{%4,%5,%6,%7},{%8,%9},{%0,%1,%2,%3};"
        : "+f"(d.x), "+f"(d.y), "+f"(d.z), "+f"(d.w)
        : "r"(a0), "r"(a1), "r"(a2), "r"(a3), "r"(b0), "r"(b1));
}

// ---------------------------------------------------------------------------
// GEMM: C[b][o][n] = sum_c W[o][c] * In[b][c][n]  (fp32 / FFMA2)
// MODE 0: QKV. q,k written [bh][n][d]; v written [bh][d][n].
// MODE 1: out-proj, reads g_o [b][c][n], writes d_out.
// ---------------------------------------------------------------------------
template <int MODE>
__global__ void __launch_bounds__(256) gemm_kernel(const float* __restrict__ In,
                                                   const float* __restrict__ W,
                                                   float* __restrict__ Out) {
    __shared__ float As[16 * 132];
    __shared__ float Bs[16 * 132];

    const int t = threadIdx.x;
    const float* src = (MODE == 0) ? In : g_o;
    const float* Wt  = W + (size_t)(blockIdx.y * 128) * CDIM;
    const float* Xt  = src + (size_t)blockIdx.z * CDIM * NSP + blockIdx.x * 128;

    const int wr = t >> 1;
    const int wc = (t & 1) * 8;
    const int br = t >> 4;
    const int bc = (t & 15) * 8;
    const int o0 = (t >> 4) * 8;
    const int n0 = (t & 15) * 8;

    ull acc[8][4];
#pragma unroll
    for (int i = 0; i < 8; i++)
#pragma unroll
        for (int m = 0; m < 4; m++) acc[i][m] = 0ULL;

    for (int kt = 0; kt < CDIM; kt += 16) {
        float4 w0 = *(const float4*)&Wt[(size_t)wr * CDIM + kt + wc];
        float4 w1 = *(const float4*)&Wt[(size_t)wr * CDIM + kt + wc + 4];
        As[(wc + 0) * 132 + wr] = w0.x;
        As[(wc + 1) * 132 + wr] = w0.y;
        As[(wc + 2) * 132 + wr] = w0.z;
        As[(wc + 3) * 132 + wr] = w0.w;
        As[(wc + 4) * 132 + wr] = w1.x;
        As[(wc + 5) * 132 + wr] = w1.y;
        As[(wc + 6) * 132 + wr] = w1.z;
        As[(wc + 7) * 132 + wr] = w1.w;
        *(float4*)&Bs[br * 132 + bc] =
            *(const float4*)&Xt[(size_t)(kt + br) * NSP + bc];
        *(float4*)&Bs[br * 132 + bc + 4] =
            *(const float4*)&Xt[(size_t)(kt + br) * NSP + bc + 4];
        __syncthreads();
#pragma unroll
        for (int kk = 0; kk < 16; kk++) {
            float4 a0 = *(float4*)&As[kk * 132 + o0];
            float4 a1 = *(float4*)&As[kk * 132 + o0 + 4];
            const ull* bp = (const ull*)&Bs[kk * 132 + n0];
            ull b0 = bp[0], b1 = bp[1], b2 = bp[2], b3 = bp[3];
            float av[8] = {a0.x, a0.y, a0.z, a0.w, a1.x, a1.y, a1.z, a1.w};
#pragma unroll
            for (int i = 0; i < 8; i++) {
                ull ai = pk2(av[i], av[i]);
                acc[i][0] = ffma2(ai, b0, acc[i][0]);
                acc[i][1] = ffma2(ai, b1, acc[i][1]);
                acc[i][2] = ffma2(ai, b2, acc[i][2]);
                acc[i][3] = ffma2(ai, b3, acc[i][3]);
            }
        }
        __syncthreads();
    }

    const int n = blockIdx.x * 128 + n0;
    if (MODE == 0) {
        const int s  = blockIdx.y >> 2;            // 4 y-blocks per s
        const int od = (blockIdx.y & 3) * 128 + o0;
        if (s < 2) {
            // q,k -> [bh][n][d]
            float* dst = (s == 0) ? g_q : g_k;
            const int h  = od >> 6;
            const int d0 = od & 63;
            float av[8][8];
#pragma unroll
            for (int i = 0; i < 8; i++)
#pragma unroll
                for (int m = 0; m < 4; m++)
                    upk2(acc[i][m], av[i][2 * m], av[i][2 * m + 1]);
            const size_t base =
                ((size_t)(blockIdx.z * NHEAD + h) * NSP + n) * 64 + d0;
#pragma unroll
            for (int j = 0; j < 8; j++) {
                *(float4*)&dst[base + (size_t)j * 64] =
                    make_float4(av[0][j], av[1][j], av[2][j], av[3][j]);
                *(float4*)&dst[base + (size_t)j * 64 + 4] =
                    make_float4(av[4][j], av[5][j], av[6][j], av[7][j]);
            }
        } else {
            // v -> [bh][d][n]
#pragma unroll
            for (int i = 0; i < 8; i++) {
                const size_t row = (size_t)blockIdx.z * 512 + od + i;
#pragma unroll
                for (int m = 0; m < 4; m++) {
                    float lo, hi; upk2(acc[i][m], lo, hi);
                    *(float2*)&g_v[row * NSP + n + 2 * m] = make_float2(lo, hi);
                }
            }
        }
    } else {
#pragma unroll
        for (int i = 0; i < 8; i++) {
            const size_t row = (size_t)blockIdx.z * CDIM + blockIdx.y * 128 + o0 + i;
#pragma unroll
            for (int m = 0; m < 4; m++) {
                float lo, hi; upk2(acc[i][m], lo, hi);
                *(float2*)&Out[row * NSP + n + 2 * m] = make_float2(lo, hi);
            }
        }
    }
}

// ---------------------------------------------------------------------------
// RoPE on q,k in place, layout [bh][n][d]; pair (j, j+32).
// ---------------------------------------------------------------------------
__global__ void __launch_bounds__(256) rope_kernel() {
    const int idx = blockIdx.x * 256 + threadIdx.x;
    const int j   = idx & 31;
    const int n   = (idx >> 5) & (NSP - 1);
    const int bh  = idx >> 17;

    const int ph = n >> 6;
    const int pw = n & 63;
    const float jf  = (float)(j < 16 ? j : j - 16);
    const float pos = (float)(j < 16 ? ph : pw);
    const float freq = exp2f(-0.8304820237218406f * jf);
    const float ang  = pos * freq;
    float sn, cs;
    sincosf(ang, &sn, &cs);

    const size_t base = ((size_t)bh << 18) + (size_t)n * 64;
    const size_t i1 = base + j;
    const size_t i2 = base + j + 32;

    float q1 = g_q[i1], q2 = g_q[i2];
    g_q[i1] = q1 * cs - q2 * sn;
    g_q[i2] = q1 * sn + q2 * cs;
    float k1 = g_k[i1], k2 = g_k[i2];
    g_k[i1] = k1 * cs - k2 * sn;
    g_k[i2] = k1 * sn + k2 * cs;
}

// ---------------------------------------------------------------------------
// Flash attention, tf32 mma.sync. BR=BC=128, 256 threads = 8 warps.
// Warp w owns rows 16w..16w+15 for the whole kt loop:
//   softmax stats + O accumulator stay in registers.
// Smem (tf32 bits): Qs[r][d] s68, Ks[c][d] s68, Vs[d][c] s132, Ps[r][c] s132.
// ---------------------------------------------------------------------------
#define QS_OFF  0
#define KS_OFF  8704
#define VS_OFF  17408
#define PS_OFF  25856
#define ATTN_SMEM ((25856 + 128 * 132) * 4)   // 171008 B

#define SCALE 0.18033688011112042f   // hd^-1/2 * log2(e)

__global__ void __launch_bounds__(256) attn_kernel() {
    extern __shared__ unsigned sm[];
    unsigned* Qs = sm + QS_OFF;
    unsigned* Ks = sm + KS_OFF;
    unsigned* Vs = sm + VS_OFF;
    unsigned* Ps = sm + PS_OFF;

    const int t    = threadIdx.x;
    const int lane = t & 31;
    const int g    = lane >> 2;
    const int tq   = lane & 3;
    const int rw   = (t >> 5) * 16;
    const int bh   = blockIdx.y;
    const int ntile = blockIdx.x * 128;

    const float* Qg = g_q + ((size_t)bh << 18) + (size_t)ntile * 64;
    const float* Kg = g_k + ((size_t)bh << 18);
    const float* Vg = g_v + (size_t)bh * (HD * NSP);

    // Q fill: [r][d], scaled + tf32
    {
        const int r = t >> 1, dh = (t & 1) * 32;
        const float* src = Qg + (size_t)r * 64 + dh;
        unsigned* dst = Qs + r * 68 + dh;
#pragma unroll
        for (int c = 0; c < 8; c++) {
            float4 v = *(const float4*)(src + c * 4);
            dst[c * 4 + 0] = cvt_tf32(v.x * SCALE);
            dst[c * 4 + 1] = cvt_tf32(v.y * SCALE);
            dst[c * 4 + 2] = cvt_tf32(v.z * SCALE);
            dst[c * 4 + 3] = cvt_tf32(v.w * SCALE);
        }
    }

    float4 o[8];
#pragma unroll
    for (int jt = 0; jt < 8; jt++) o[jt] = make_float4(0.f, 0.f, 0.f, 0.f);
    float m0 = -1e30f, m1 = -1e30f, l0 = 0.f, l1 = 0.f;

    for (int kt = 0; kt < 32; kt++) {
        __syncthreads();
        // K fill: [c][d]
        {
            const int c = t >> 1, dh = (t & 1) * 32;
            const float* src = Kg + (size_t)(kt * 128 + c) * 64 + dh;
            unsigned* dst = Ks + c * 68 + dh;
#pragma unroll
            for (int cc = 0; cc < 8; cc++) {
                float4 v = *(const float4*)(src + cc * 4);
                dst[cc * 4 + 0] = cvt_tf32(v.x);
                dst[cc * 4 + 1] = cvt_tf32(v.y);
                dst[cc * 4 + 2] = cvt_tf32(v.z);
                dst[cc * 4 + 3] = cvt_tf32(v.w);
            }
        }
        // V fill: [d][c]
        {
            const int d = t >> 2, cq = (t & 3) * 32;
            const float* src = Vg + (size_t)d * NSP + kt * 128 + cq;
            unsigned* dst = Vs + d * 132 + cq;
#pragma unroll
            for (int cc = 0; cc < 8; cc++) {
                float4 v = *(const float4*)(src + cc * 4);
                dst[cc * 4 + 0] = cvt_tf32(v.x);
                dst[cc * 4 + 1] = cvt_tf32(v.y);
                dst[cc * 4 + 2] = cvt_tf32(v.z);
                dst[cc * 4 + 3] = cvt_tf32(v.w);
            }
        }
        __syncthreads();

        // ---- S = Q K^T ----
        float4 s[16];
#pragma unroll
        for (int j = 0; j < 16; j++) s[j] = make_float4(0.f, 0.f, 0.f, 0.f);
#pragma unroll
        for (int k8 = 0; k8 < 8; k8++) {
            const unsigned* qp = Qs + (rw + g) * 68 + k8 * 8 + tq;
            unsigned a0 = qp[0], a2 = qp[4];
            unsigned a1 = qp[8 * 68], a3 = qp[8 * 68 + 4];
#pragma unroll
            for (int j = 0; j < 16; j++) {
                const unsigned* kp = Ks + (j * 8 + g) * 68 + k8 * 8 + tq;
                mma8(s[j], a0, a1, a2, a3, kp[0], kp[4]);
            }
        }

        // ---- online softmax (register-resident stats) ----
        float nm0 = -1e30f, nm1 = -1e30f;
#pragma unroll
        for (int j = 0; j < 16; j++) {
            nm0 = fmaxf(nm0, fmaxf(s[j].x, s[j].y));
            nm1 = fmaxf(nm1, fmaxf(s[j].z, s[j].w));
        }
        nm0 = fmaxf(nm0, __shfl_xor_sync(0xffffffffu, nm0, 1));
        nm0 = fmaxf(nm0, __shfl_xor_sync(0xffffffffu, nm0, 2));
        nm1 = fmaxf(nm1, __shfl_xor_sync(0xffffffffu, nm1, 1));
        nm1 = fmaxf(nm1, __shfl_xor_sync(0xffffffffu, nm1, 2));
        const float mn0 = fmaxf(m0, nm0), mn1 = fmaxf(m1, nm1);
        const float cr0 = ex2(m0 - mn0), cr1 = ex2(m1 - mn1);
        m0 = mn0; m1 = mn1;
        float s0 = 0.f, s1 = 0.f;
#pragma unroll
        for (int j = 0; j < 16; j++) {
            s[j].x = ex2(s[j].x - mn0);
            s[j].y = ex2(s[j].y - mn0);
            s[j].z = ex2(s[j].z - mn1);
            s[j].w = ex2(s[j].w - mn1);
            s0 += s[j].x + s[j].y;
            s1 += s[j].z + s[j].w;
        }
        s0 += __shfl_xor_sync(0xffffffffu, s0, 1);
        s0 += __shfl_xor_sync(0xffffffffu, s0, 2);
        s1 += __shfl_xor_sync(0xffffffffu, s1, 1);
        s1 += __shfl_xor_sync(0xffffffffu, s1, 2);
        l0 = l0 * cr0 + s0;
        l1 = l1 * cr1 + s1;
#pragma unroll
        for (int jt = 0; jt < 8; jt++) {
            o[jt].x *= cr0; o[jt].y *= cr0;
            o[jt].z *= cr1; o[jt].w *= cr1;
        }

        // ---- P -> smem (tf32) ----
        {
            unsigned* pr0 = Ps + (rw + g) * 132 + 2 * tq;
            unsigned* pr1 = Ps + (rw + g + 8) * 132 + 2 * tq;
#pragma unroll
            for (int j = 0; j < 16; j++) {
                uint2 u0 = make_uint2(cvt_tf32(s[j].x), cvt_tf32(s[j].y));
                uint2 u1 = make_uint2(cvt_tf32(s[j].z), cvt_tf32(s[j].w));
                *(uint2*)(pr0 + 8 * j) = u0;
                *(uint2*)(pr1 + 8 * j) = u1;
            }
        }
        __syncwarp();

        // ---- O += P V ----
#pragma unroll
        for (int kc = 0; kc < 16; kc++) {
            const unsigned* pa = Ps + (rw + g) * 132 + kc * 8 + tq;
            unsigned a0 = pa[0], a2 = pa[4];
            unsigned a1 = pa[8 * 132], a3 = pa[8 * 132 + 4];
#pragma unroll
            for (int jt = 0; jt < 8; jt++) {
                const unsigned* vp = Vs + (jt * 8 + g) * 132 + kc * 8 + tq;
                mma8(o[jt], a0, a1, a2, a3, vp[0], vp[4]);
            }
        }
    }

    // ---- epilogue: /l, write g_o[b][c][n] ----
    const float i0 = 1.0f / l0, i1 = 1.0f / l1;
#pragma unroll
    for (int jt = 0; jt < 8; jt++) {
        const size_t base =
            ((size_t)bh * 64 + jt * 8 + 2 * tq) * NSP + ntile + rw + g;
        g_o[base]           = o[jt].x * i0;
        g_o[base + NSP]     = o[jt].y * i0;
        g_o[base + 8]       = o[jt].z * i1;
        g_o[base + NSP + 8] = o[jt].w * i1;
    }
}

// ---------------------------------------------------------------------------
extern "C" void kernel_launch(void* const* d_in, const int* in_sizes, int n_in,
                              void* d_out, int out_size) {
    const float* x      = (const float*)d_in[0];
    const float* w_qkv  = (const float*)d_in[1];
    const float* w_proj = (const float*)d_in[2];
    float* out = (float*)d_out;

    cudaFuncSetAttribute(attn_kernel,
                         cudaFuncAttributeMaxDynamicSharedMemorySize, ATTN_SMEM);

    gemm_kernel<0><<<dim3(NSP / 128, 12, NB), 256>>>(x, w_qkv, nullptr);
    rope_kernel<<<(NBH * 32 * NSP) / 256, 256>>>();
    attn_kernel<<<dim3(NSP / 128, NBH), 256, ATTN_SMEM>>>();
    gemm_kernel<1><<<dim3(NSP / 128, 4, NB), 256>>>(nullptr, w_proj, out);
}

// round 6
// speedup vs baseline: 4.7861x; 2.2068x over previous
#include <cuda_runtime.h>

#define NB    4
#define CDIM  512
#define NHEAD 8
#define HD    64
#define NSP   4096
#define NBH   (NB*NHEAD)

// q,k: [bh][n][d]   v: [bh][d][n]   o: [b][c][n]
__device__ float g_q[NBH * NSP * HD];
__device__ float g_k[NBH * NSP * HD];
__device__ float g_v[NBH * HD * NSP];
__device__ float g_o[NB * CDIM * NSP];

// ---- helpers ----
__device__ __forceinline__ unsigned cvt_tf32(float f) {
    unsigned r; asm("cvt.rna.tf32.f32 %0,%1;" : "=r"(r) : "f"(f)); return r;
}
__device__ __forceinline__ unsigned h2pk(float lo, float hi) {
    unsigned r; asm("cvt.rn.f16x2.f32 %0,%1,%2;" : "=r"(r) : "f"(hi), "f"(lo)); return r;
}
__device__ __forceinline__ float ex2(float x) {
    float r; asm("ex2.approx.f32 %0,%1;" : "=f"(r) : "f"(x)); return r;
}
// tf32 m16n8k8: a1 = row+8, a2 = col+4
__device__ __forceinline__ void mma8(float4& d, unsigned a0, unsigned a1,
                                     unsigned a2, unsigned a3,
                                     unsigned b0, unsigned b1) {
    asm("mma.sync.aligned.m16n8k8.row.col.f32.tf32.tf32.f32 "
        "{%0,%1,%2,%3},{%4,%5,%6,%7},{%8,%9},{%0,%1,%2,%3};"
        : "+f"(d.x), "+f"(d.y), "+f"(d.z), "+f"(d.w)
        : "r"(a0), "r"(a1), "r"(a2), "r"(a3), "r"(b0), "r"(b1));
}
// fp16 m16n8k16: a0={A[g][2tq..+1]}, a1=row+8, a2=col+8, a3=row+8,col+8
__device__ __forceinline__ void mma16(float4& d, unsigned a0, unsigned a1,
                                      unsigned a2, unsigned a3,
                                      unsigned b0, unsigned b1) {
    asm("mma.sync.aligned.m16n8k16.row.col.f32.f16.f16.f32 "
        "{%0,%1,%2,%3},{%4,%5,%6,%7},{%8,%9},{%0,%1,%2,%3};"
        : "+f"(d.x), "+f"(d.y), "+f"(d.z), "+f"(d.w)
        : "r"(a0), "r"(a1), "r"(a2), "r"(a3), "r"(b0), "r"(b1));
}

// ---------------------------------------------------------------------------
// tf32 tensor GEMM: C[b][o][n] = sum_c W[o][c] * In[b][c][n]
// 128x128 tile, KT=16, 8 warps in 2x4 grid (warp tile 64x32).
// As[o][k] stride 20 uints, Bs[n][k] stride 20 uints.
// MODE 0: QKV -> q,k [bh][n][d]; v [bh][d][n].  MODE 1: out-proj.
// ---------------------------------------------------------------------------
template <int MODE>
__global__ void __launch_bounds__(256, 2) gemm_kernel(const float* __restrict__ In,
                                                      const float* __restrict__ W,
                                                      float* __restrict__ Out) {
    __shared__ unsigned As[128 * 20];
    __shared__ unsigned Bs[128 * 20];

    const int t    = threadIdx.x;
    const int lane = t & 31;
    const int g    = lane >> 2;
    const int tq   = lane & 3;
    const int w    = t >> 5;
    const int wr   = (w >> 2) * 64;
    const int wn   = (w & 3) * 32;

    const float* src = (MODE == 0) ? In : g_o;
    const float* Wt  = W + (size_t)(blockIdx.y * 128) * CDIM;
    const float* Xt  = src + (size_t)blockIdx.z * CDIM * NSP + blockIdx.x * 128;

    const int fo = t >> 1, fk = (t & 1) * 8;       // W fill
    const int xn = t & 127, xk = (t >> 7) * 8;     // X fill

    float4 acc[4][4];
#pragma unroll
    for (int i = 0; i < 4; i++)
#pragma unroll
        for (int j = 0; j < 4; j++) acc[i][j] = make_float4(0.f, 0.f, 0.f, 0.f);

    for (int kt = 0; kt < CDIM; kt += 16) {
        // W tile -> As[o][k]
        float4 w0 = *(const float4*)&Wt[(size_t)fo * CDIM + kt + fk];
        float4 w1 = *(const float4*)&Wt[(size_t)fo * CDIM + kt + fk + 4];
        uint4 u0 = make_uint4(cvt_tf32(w0.x), cvt_tf32(w0.y), cvt_tf32(w0.z), cvt_tf32(w0.w));
        uint4 u1 = make_uint4(cvt_tf32(w1.x), cvt_tf32(w1.y), cvt_tf32(w1.z), cvt_tf32(w1.w));
        *(uint4*)&As[fo * 20 + fk]     = u0;
        *(uint4*)&As[fo * 20 + fk + 4] = u1;
        // X tile -> Bs[n][k] (transposed fill: one n-column per thread)
        unsigned xv[8];
#pragma unroll
        for (int i = 0; i < 8; i++)
            xv[i] = cvt_tf32(Xt[(size_t)(kt + xk + i) * NSP + xn]);
        *(uint4*)&Bs[xn * 20 + xk]     = make_uint4(xv[0], xv[1], xv[2], xv[3]);
        *(uint4*)&Bs[xn * 20 + xk + 4] = make_uint4(xv[4], xv[5], xv[6], xv[7]);
        __syncthreads();

#pragma unroll
        for (int k8 = 0; k8 < 2; k8++) {
            unsigned a[4][4];
#pragma unroll
            for (int mt = 0; mt < 4; mt++) {
                const unsigned* p = As + (wr + mt * 16 + g) * 20 + k8 * 8 + tq;
                a[mt][0] = p[0]; a[mt][1] = p[160]; a[mt][2] = p[4]; a[mt][3] = p[164];
            }
            unsigned b[4][2];
#pragma unroll
            for (int nt = 0; nt < 4; nt++) {
                const unsigned* p = Bs + (wn + nt * 8 + g) * 20 + k8 * 8 + tq;
                b[nt][0] = p[0]; b[nt][1] = p[4];
            }
#pragma unroll
            for (int mt = 0; mt < 4; mt++)
#pragma unroll
                for (int nt = 0; nt < 4; nt++)
                    mma8(acc[mt][nt], a[mt][0], a[mt][1], a[mt][2], a[mt][3],
                         b[nt][0], b[nt][1]);
        }
        __syncthreads();
    }

    // epilogue
#pragma unroll
    for (int mt = 0; mt < 4; mt++) {
#pragma unroll
        for (int nt = 0; nt < 4; nt++) {
            const float4 c = acc[mt][nt];
            const int ol = wr + mt * 16 + g;
            const int n  = blockIdx.x * 128 + wn + nt * 8 + 2 * tq;
            if (MODE == 0) {
                const int o = blockIdx.y * 128 + ol;
                const int s = o >> 9;
                if (s < 2) {
                    float* dst = (s == 0) ? g_q : g_k;
                    const int h = (o >> 6) & 7;
                    const int d = o & 63;
                    const size_t b0 =
                        ((size_t)(blockIdx.z * NHEAD + h) * NSP + n) * 64 + d;
                    dst[b0]          = c.x;
                    dst[b0 + 64]     = c.y;
                    dst[b0 + 8]      = c.z;   // row +8 -> d+8 (same head)
                    dst[b0 + 64 + 8] = c.w;
                } else {
                    const size_t row = (size_t)blockIdx.z * 512 + (o & 511);
                    *(float2*)&g_v[row * NSP + n]       = make_float2(c.x, c.y);
                    *(float2*)&g_v[(row + 8) * NSP + n] = make_float2(c.z, c.w);
                }
            } else {
                const size_t row =
                    (size_t)blockIdx.z * CDIM + blockIdx.y * 128 + ol;
                *(float2*)&Out[row * NSP + n]       = make_float2(c.x, c.y);
                *(float2*)&Out[(row + 8) * NSP + n] = make_float2(c.z, c.w);
            }
        }
    }
}

// ---------------------------------------------------------------------------
// RoPE on q,k in place, layout [bh][n][d]; pair (j, j+32).
// ---------------------------------------------------------------------------
__global__ void __launch_bounds__(256) rope_kernel() {
    const int idx = blockIdx.x * 256 + threadIdx.x;
    const int j   = idx & 31;
    const int n   = (idx >> 5) & (NSP - 1);
    const int bh  = idx >> 17;

    const int ph = n >> 6;
    const int pw = n & 63;
    const float jf  = (float)(j < 16 ? j : j - 16);
    const float pos = (float)(j < 16 ? ph : pw);
    const float freq = exp2f(-0.8304820237218406f * jf);
    const float ang  = pos * freq;
    float sn, cs;
    sincosf(ang, &sn, &cs);

    const size_t base = ((size_t)bh << 18) + (size_t)n * 64;
    const size_t i1 = base + j;
    const size_t i2 = base + j + 32;

    float q1 = g_q[i1], q2 = g_q[i2];
    g_q[i1] = q1 * cs - q2 * sn;
    g_q[i2] = q1 * sn + q2 * cs;
    float k1 = g_k[i1], k2 = g_k[i2];
    g_k[i1] = k1 * cs - k2 * sn;
    g_k[i2] = k1 * sn + k2 * cs;
}

// ---------------------------------------------------------------------------
// Flash attention, fp16 mma.m16n8k16, fp32 accum. BR=BC=128, 8 warps.
// Qs/Ks: [row][72 halves] (36 uints). Vs: [cp][72 uints], cp = c/2,
//   word = half2(V[2cp][d], V[2cp+1][d]) at d ^ (((cp>>4)&3)<<3).
// P stays in registers (S-accum fragments == A-operand fragments).
// ---------------------------------------------------------------------------
#define ATTN_SMEM (13824 * 4)   // Qs 4608 + Ks 4608 + Vs 4608 uints

#define SCALE 0.18033688011112042f   // hd^-1/2 * log2(e)

__global__ void __launch_bounds__(256, 2) attn_kernel() {
    extern __shared__ unsigned smu[];
    unsigned* Qs = smu;
    unsigned* Ks = smu + 4608;
    unsigned* Vs = smu + 9216;

    const int t    = threadIdx.x;
    const int lane = t & 31;
    const int g    = lane >> 2;
    const int tq   = lane & 3;
    const int rw   = (t >> 5) * 16;
    const int bh   = blockIdx.y;
    const int ntile = blockIdx.x * 128;

    const float* Qg = g_q + ((size_t)bh << 18) + (size_t)ntile * 64;
    const float* Kg = g_k + ((size_t)bh << 18);
    const float* Vg = g_v + (size_t)bh * (HD * NSP);

    // Q fill: [r][d] halves, scale folded
    {
        const int r = t >> 1, seg = t & 1;
        const float* src = Qg + (size_t)r * 64 + seg * 32;
        unsigned* dst = Qs + r * 36 + seg * 16;
#pragma unroll
        for (int c = 0; c < 8; c++) {
            float4 v = *(const float4*)(src + c * 4);
            dst[2 * c]     = h2pk(v.x * SCALE, v.y * SCALE);
            dst[2 * c + 1] = h2pk(v.z * SCALE, v.w * SCALE);
        }
    }

    float4 o[8];
#pragma unroll
    for (int jt = 0; jt < 8; jt++) o[jt] = make_float4(0.f, 0.f, 0.f, 0.f);
    float m0 = -1e30f, m1 = -1e30f, l0 = 0.f, l1 = 0.f;

    const int vd = t >> 2, vq = t & 3;   // V fill coords

    for (int kt = 0; kt < 32; kt++) {
        __syncthreads();   // previous iter's smem reads done
        // K fill: [c][d]
        {
            const int r = t >> 1, seg = t & 1;
            const float* src = Kg + (size_t)(kt * 128 + r) * 64 + seg * 32;
            unsigned* dst = Ks + r * 36 + seg * 16;
#pragma unroll
            for (int c = 0; c < 8; c++) {
                float4 v = *(const float4*)(src + c * 4);
                dst[2 * c]     = h2pk(v.x, v.y);
                dst[2 * c + 1] = h2pk(v.z, v.w);
            }
        }
        // V fill: interleaved pairs, XOR swizzle on d
        {
            const float* src = Vg + (size_t)vd * NSP + kt * 128;
#pragma unroll
            for (int i = 0; i < 8; i++) {
                const int n = 4 * vq + 16 * i;
                float4 v = *(const float4*)(src + n);
                const int cp = n >> 1;
                const int sz = ((cp >> 4) & 3) << 3;
                Vs[cp * 72 + (vd ^ sz)]       = h2pk(v.x, v.y);
                Vs[(cp + 1) * 72 + (vd ^ sz)] = h2pk(v.z, v.w);
            }
        }
        __syncthreads();

        // ---- S = Q K^T ----
        float4 s[16];
#pragma unroll
        for (int j = 0; j < 16; j++) s[j] = make_float4(0.f, 0.f, 0.f, 0.f);
#pragma unroll
        for (int k16 = 0; k16 < 4; k16++) {
            const unsigned* qp = Qs + (rw + g) * 36 + k16 * 8 + tq;
            unsigned a0 = qp[0], a1 = qp[8 * 36], a2 = qp[4], a3 = qp[8 * 36 + 4];
#pragma unroll
            for (int j = 0; j < 16; j++) {
                const unsigned* kp = Ks + (j * 8 + g) * 36 + k16 * 8 + tq;
                mma16(s[j], a0, a1, a2, a3, kp[0], kp[4]);
            }
        }

        // ---- online softmax (register stats) + pack P to fp16 frags ----
        float nm0 = -1e30f, nm1 = -1e30f;
#pragma unroll
        for (int j = 0; j < 16; j++) {
            nm0 = fmaxf(nm0, fmaxf(s[j].x, s[j].y));
            nm1 = fmaxf(nm1, fmaxf(s[j].z, s[j].w));
        }
        nm0 = fmaxf(nm0, __shfl_xor_sync(0xffffffffu, nm0, 1));
        nm0 = fmaxf(nm0, __shfl_xor_sync(0xffffffffu, nm0, 2));
        nm1 = fmaxf(nm1, __shfl_xor_sync(0xffffffffu, nm1, 1));
        nm1 = fmaxf(nm1, __shfl_xor_sync(0xffffffffu, nm1, 2));
        const float mn0 = fmaxf(m0, nm0), mn1 = fmaxf(m1, nm1);
        const float cr0 = ex2(m0 - mn0), cr1 = ex2(m1 - mn1);
        m0 = mn0; m1 = mn1;

        unsigned pa[16], pb[16];
        float s0 = 0.f, s1 = 0.f;
#pragma unroll
        for (int j = 0; j < 16; j++) {
            float e0 = ex2(s[j].x - mn0);
            float e1 = ex2(s[j].y - mn0);
            float e2 = ex2(s[j].z - mn1);
            float e3 = ex2(s[j].w - mn1);
            s0 += e0 + e1;
            s1 += e2 + e3;
            pa[j] = h2pk(e0, e1);
            pb[j] = h2pk(e2, e3);
        }
        s0 += __shfl_xor_sync(0xffffffffu, s0, 1);
        s0 += __shfl_xor_sync(0xffffffffu, s0, 2);
        s1 += __shfl_xor_sync(0xffffffffu, s1, 1);
        s1 += __shfl_xor_sync(0xffffffffu, s1, 2);
        l0 = l0 * cr0 + s0;
        l1 = l1 * cr1 + s1;
#pragma unroll
        for (int jt = 0; jt < 8; jt++) {
            o[jt].x *= cr0; o[jt].y *= cr0;
            o[jt].z *= cr1; o[jt].w *= cr1;
        }

        // ---- O += P V (P from registers; V frags from swizzled smem) ----
#pragma unroll
        for (int kc = 0; kc < 8; kc++) {
            unsigned a0 = pa[2 * kc], a1 = pb[2 * kc];
            unsigned a2 = pa[2 * kc + 1], a3 = pb[2 * kc + 1];
            const int cp0 = kc * 8 + tq, cp1 = cp0 + 4;
            const unsigned* v0 = Vs + cp0 * 72;
            const unsigned* v1 = Vs + cp1 * 72;
            const int sz0 = ((cp0 >> 4) & 3) << 3;
            const int sz1 = ((cp1 >> 4) & 3) << 3;
#pragma unroll
            for (int jt = 0; jt < 8; jt++) {
                const int d = jt * 8 + g;
                mma16(o[jt], a0, a1, a2, a3, v0[d ^ sz0], v1[d ^ sz1]);
            }
        }
    }

    // ---- epilogue: /l, write g_o[b][c][n] ----
    const float i0 = 1.0f / l0, i1 = 1.0f / l1;
#pragma unroll
    for (int jt = 0; jt < 8; jt++) {
        const int d0 = jt * 8 + 2 * tq;
        const size_t base = ((size_t)bh * 64 + d0) * NSP + ntile + rw + g;
        g_o[base]            = o[jt].x * i0;
        g_o[base + NSP]      = o[jt].y * i0;
        g_o[base + 8]        = o[jt].z * i1;
        g_o[base + NSP + 8]  = o[jt].w * i1;
    }
}

// ---------------------------------------------------------------------------
extern "C" void kernel_launch(void* const* d_in, const int* in_sizes, int n_in,
                              void* d_out, int out_size) {
    const float* x      = (const float*)d_in[0];
    const float* w_qkv  = (const float*)d_in[1];
    const float* w_proj = (const float*)d_in[2];
    float* out = (float*)d_out;

    cudaFuncSetAttribute(attn_kernel,
                         cudaFuncAttributeMaxDynamicSharedMemorySize, ATTN_SMEM);

    gemm_kernel<0><<<dim3(NSP / 128, 12, NB), 256>>>(x, w_qkv, nullptr);
    rope_kernel<<<(NBH * 32 * NSP) / 256, 256>>>();
    attn_kernel<<<dim3(NSP / 128, NBH), 256, ATTN_SMEM>>>();
    gemm_kernel<1><<<dim3(NSP / 128, 4, NB), 256>>>(nullptr, w_proj, out);
}

// round 7
// speedup vs baseline: 6.6015x; 1.3793x over previous
#include <cuda_runtime.h>
#include <cuda_fp16.h>

#define NB    4
#define CDIM  512
#define NHEAD 8
#define HD    64
#define NSP   4096
#define NBH   32

// fp16 storage, addressed as uint = half2 pair (low = even index)
__device__ unsigned g_xh[NB * NSP * 256];    // x^T  [b][n][c/2]
__device__ unsigned g_wh[1536 * 256];        // w_qkv [o][c/2]
__device__ unsigned g_wph[512 * 256];        // w_proj [o][c/2]
__device__ unsigned g_qh[NBH * NSP * 32];    // [bh][n][d/2]
__device__ unsigned g_kh[NBH * NSP * 32];
__device__ unsigned g_vh[NBH * NSP * 32];
__device__ unsigned g_oh[NB * NSP * 256];    // attn out [b][n][c/2]

// ---- helpers ----
__device__ __forceinline__ unsigned h2pk(float lo, float hi) {
    unsigned r; asm("cvt.rn.f16x2.f32 %0,%1,%2;" : "=r"(r) : "f"(hi), "f"(lo)); return r;
}
__device__ __forceinline__ float ex2(float x) {
    float r; asm("ex2.approx.f32 %0,%1;" : "=f"(r) : "f"(x)); return r;
}
__device__ __forceinline__ void mma16(float4& d, unsigned a0, unsigned a1,
                                      unsigned a2, unsigned a3,
                                      unsigned b0, unsigned b1) {
    asm("mma.sync.aligned.m16n8k16.row.col.f32.f16.f16.f32 "
        "{%0,%1,%2,%3},{%4,%5,%6,%7},{%8,%9},{%0,%1,%2,%3};"
        : "+f"(d.x), "+f"(d.y), "+f"(d.z), "+f"(d.w)
        : "r"(a0), "r"(a1), "r"(a2), "r"(a3), "r"(b0), "r"(b1));
}
__device__ __forceinline__ void cpa16(unsigned dst, const void* src) {
    asm volatile("cp.async.cg.shared.global [%0], [%1], 16;"
                 :: "r"(dst), "l"(src) : "memory");
}
#define CP_COMMIT() asm volatile("cp.async.commit_group;" ::: "memory")
#define CP_WAIT1()  asm volatile("cp.async.wait_group 1;" ::: "memory")

// ---------------------------------------------------------------------------
// One-time converts
// ---------------------------------------------------------------------------
__global__ void __launch_bounds__(256) f2h_kernel(const float* __restrict__ src,
                                                  int which) {
    unsigned* dst = which ? g_wph : g_wh;
    const int i = blockIdx.x * 256 + threadIdx.x;
    float2 v = ((const float2*)src)[i];
    dst[i] = h2pk(v.x, v.y);
}

// x [b][c][n] f32 -> g_xh [b][n][c/2] f16 (transpose via smem tile)
__global__ void __launch_bounds__(256) convx_kernel(const float* __restrict__ x) {
    __shared__ float ts[32][33];
    const int t = threadIdx.x;
    const int n0 = blockIdx.x * 32, c0 = blockIdx.y * 32, b = blockIdx.z;
    const int tx = t & 31, ty = t >> 5;
    const float* xp = x + ((size_t)b * CDIM + c0) * NSP + n0;
#pragma unroll
    for (int i = 0; i < 4; i++)
        ts[ty + 8 * i][tx] = xp[(size_t)(ty + 8 * i) * NSP + tx];
    __syncthreads();
    const int r = t >> 4, cp = t & 15;
#pragma unroll
    for (int i = 0; i < 2; i++) {
        const int rr = r + 16 * i;
        g_xh[((size_t)b * NSP + n0 + rr) * 256 + (c0 >> 1) + cp] =
            h2pk(ts[2 * cp][rr], ts[2 * cp + 1][rr]);
    }
}

// ---------------------------------------------------------------------------
// fp16 tensor GEMM, 128x128 tile, KT=64, cp.async 2-stage double buffer.
// Smem per stage: A 128x36 uints, B 128x36 uints.
// MODE 0: A = g_xh (m=token rows), B = g_wh (o rows); out q/k/v [bh][n][d] f16.
// MODE 1: A = g_wph (m=o rows),   B = g_oh (token rows); out f32 [b][o][n].
// ---------------------------------------------------------------------------
#define GEMM_SMEM (2 * 9216 * 4)

template <int MODE>
__global__ void __launch_bounds__(256, 2) hgemm_kernel(float* __restrict__ Out) {
    extern __shared__ unsigned sm[];
    const unsigned smb = (unsigned)__cvta_generic_to_shared(sm);

    const int t    = threadIdx.x;
    const int lane = t & 31;
    const int g    = lane >> 2;
    const int tq   = lane & 3;
    const int w    = t >> 5;
    const int wr   = (w >> 2) * 64;
    const int wn   = (w & 3) * 32;

    const unsigned* Ag;
    const unsigned* Bg;
    if (MODE == 0) {
        Ag = g_xh + ((size_t)blockIdx.z * NSP + blockIdx.x * 128) * 256;
        Bg = g_wh + (size_t)blockIdx.y * 128 * 256;
    } else {
        Ag = g_wph + (size_t)blockIdx.y * 128 * 256;
        Bg = g_oh + ((size_t)blockIdx.z * NSP + blockIdx.x * 128) * 256;
    }

    const int fr = t >> 3, fc = (t & 7) * 4;   // fill: row base, uint col

    float4 acc[4][4];
#pragma unroll
    for (int i = 0; i < 4; i++)
#pragma unroll
        for (int j = 0; j < 4; j++) acc[i][j] = make_float4(0.f, 0.f, 0.f, 0.f);

#define FILL(st, kt)                                                          \
    {                                                                         \
        _Pragma("unroll")                                                     \
        for (int i = 0; i < 4; i++) {                                         \
            const int r = fr + 32 * i;                                        \
            cpa16(smb + ((st) * 9216 + r * 36 + fc) * 4,                      \
                  Ag + (size_t)r * 256 + (kt) * 32 + fc);                     \
            cpa16(smb + ((st) * 9216 + 4608 + r * 36 + fc) * 4,               \
                  Bg + (size_t)r * 256 + (kt) * 32 + fc);                     \
        }                                                                     \
    }

    FILL(0, 0); CP_COMMIT();
    FILL(1, 1); CP_COMMIT();

    for (int kt = 0; kt < 8; kt++) {
        CP_WAIT1();
        __syncthreads();
        const unsigned* As = sm + (kt & 1) * 9216;
        const unsigned* Bs = As + 4608;
#pragma unroll
        for (int k16 = 0; k16 < 4; k16++) {
            unsigned a[4][4], b[4][2];
#pragma unroll
            for (int mt = 0; mt < 4; mt++) {
                const unsigned* p = As + (wr + mt * 16 + g) * 36 + k16 * 8 + tq;
                a[mt][0] = p[0]; a[mt][1] = p[8 * 36];
                a[mt][2] = p[4]; a[mt][3] = p[8 * 36 + 4];
            }
#pragma unroll
            for (int nt = 0; nt < 4; nt++) {
                const unsigned* p = Bs + (wn + nt * 8 + g) * 36 + k16 * 8 + tq;
                b[nt][0] = p[0]; b[nt][1] = p[4];
            }
#pragma unroll
            for (int mt = 0; mt < 4; mt++)
#pragma unroll
                for (int nt = 0; nt < 4; nt++)
                    mma16(acc[mt][nt], a[mt][0], a[mt][1], a[mt][2], a[mt][3],
                          b[nt][0], b[nt][1]);
        }
        __syncthreads();
        if (kt + 2 < 8) FILL(kt & 1, kt + 2);
        CP_COMMIT();
    }
#undef FILL

    // epilogue
#pragma unroll
    for (int mt = 0; mt < 4; mt++) {
#pragma unroll
        for (int nt = 0; nt < 4; nt++) {
            const float4 c = acc[mt][nt];
            if (MODE == 0) {
                const int o = blockIdx.y * 128 + wn + nt * 8 + 2 * tq;
                const int n = blockIdx.x * 128 + wr + mt * 16 + g;
                const int s = o >> 9, h = (o >> 6) & 7, d = o & 63;
                unsigned* dst = (s == 0) ? g_qh : (s == 1) ? g_kh : g_vh;
                const size_t base =
                    ((size_t)(blockIdx.z * NHEAD + h) * NSP + n) * 32 + (d >> 1);
                dst[base]       = h2pk(c.x, c.y);
                dst[base + 256] = h2pk(c.z, c.w);   // n+8
            } else {
                const int o = blockIdx.y * 128 + wr + mt * 16 + g;
                const int n = blockIdx.x * 128 + wn + nt * 8 + 2 * tq;
                const size_t base = ((size_t)blockIdx.z * CDIM + o) * NSP + n;
                *(float2*)&Out[base]           = make_float2(c.x, c.y);
                *(float2*)&Out[base + 8 * NSP] = make_float2(c.z, c.w);
            }
        }
    }
}

// ---------------------------------------------------------------------------
// RoPE in place on fp16 q,k [bh][n][d]; pairs (j, j+32).
// thread: (bh, n, seg); seg0 -> j in [0,16) (pos=ph), seg1 -> [16,32) (pos=pw).
// ---------------------------------------------------------------------------
__global__ void __launch_bounds__(256) rope_kernel() {
    const int idx = blockIdx.x * 256 + threadIdx.x;
    const int seg = idx & 1;
    const int n   = (idx >> 1) & (NSP - 1);
    const int bh  = idx >> 13;

    const float pos = (float)(seg ? (n & 63) : (n >> 6));
    const size_t base = ((size_t)bh * NSP + n) * 32;
    unsigned* qp = g_qh + base + 8 * seg;
    unsigned* kp = g_kh + base + 8 * seg;

#pragma unroll
    for (int i = 0; i < 8; i++) {
        const float a0 = pos * exp2f(-0.8304820237218406f * (float)(2 * i));
        const float a1 = pos * exp2f(-0.8304820237218406f * (float)(2 * i + 1));
        float s0, c0, s1, c1;
        sincosf(a0, &s0, &c0);
        sincosf(a1, &s1, &c1);

        float2 ql = __half22float2(*(__half2*)&qp[i]);
        float2 qh = __half22float2(*(__half2*)&qp[i + 16]);
        qp[i]      = h2pk(ql.x * c0 - qh.x * s0, ql.y * c1 - qh.y * s1);
        qp[i + 16] = h2pk(ql.x * s0 + qh.x * c0, ql.y * s1 + qh.y * c1);

        float2 kl = __half22float2(*(__half2*)&kp[i]);
        float2 kh = __half22float2(*(__half2*)&kp[i + 16]);
        kp[i]      = h2pk(kl.x * c0 - kh.x * s0, kl.y * c1 - kh.y * s1);
        kp[i + 16] = h2pk(kl.x * s0 + kh.x * c0, kl.y * s1 + kh.y * c1);
    }
}

// ---------------------------------------------------------------------------
// Flash attention, fp16 mma, fp32 accum. BR=BC=128, 8 warps, 2 CTAs/SM.
// Qs/Ks [row][36 uints]; Vs [cp][72 uints] c-pair interleaved + XOR swizzle.
// Scale folded into softmax exp (raw-S stats).
// ---------------------------------------------------------------------------
#define ATTN_SMEM (13824 * 4)
#define SCALE 0.18033688011112042f   // hd^-1/2 * log2(e)

__global__ void __launch_bounds__(256, 2) attn_kernel() {
    extern __shared__ unsigned smu[];
    unsigned* Qs = smu;
    unsigned* Ks = smu + 4608;
    unsigned* Vs = smu + 9216;

    const int t    = threadIdx.x;
    const int lane = t & 31;
    const int g    = lane >> 2;
    const int tq   = lane & 3;
    const int rw   = (t >> 5) * 16;
    const int bh   = blockIdx.y;
    const int ntile = blockIdx.x * 128;

    const unsigned* Qg = g_qh + ((size_t)bh * NSP + ntile) * 32;
    const unsigned* Kg = g_kh + (size_t)bh * NSP * 32;
    const unsigned* Vg = g_vh + (size_t)bh * NSP * 32;

    // Q fill: straight copy
    {
        const int r = t >> 1, sg = (t & 1) * 16;
        const uint4* src = (const uint4*)(Qg + (size_t)r * 32 + sg);
        uint4* dst = (uint4*)(Qs + r * 36 + sg);
        dst[0] = src[0]; dst[1] = src[1]; dst[2] = src[2]; dst[3] = src[3];
    }

    float4 o[8];
#pragma unroll
    for (int jt = 0; jt < 8; jt++) o[jt] = make_float4(0.f, 0.f, 0.f, 0.f);
    float m0 = -1e30f, m1 = -1e30f, l0 = 0.f, l1 = 0.f;

    for (int kt = 0; kt < 32; kt++) {
        __syncthreads();
        // K fill: straight copy
        {
            const int r = t >> 1, sg = (t & 1) * 16;
            const uint4* src = (const uint4*)(Kg + (size_t)(kt * 128 + r) * 32 + sg);
            uint4* dst = (uint4*)(Ks + r * 36 + sg);
            dst[0] = src[0]; dst[1] = src[1]; dst[2] = src[2]; dst[3] = src[3];
        }
        // V fill: repack rows (2cp, 2cp+1) into c-pair half2 words, XOR swizzle
        {
            const int cp = t >> 2, dq = t & 3;
            const unsigned* s0 = Vg + (size_t)(kt * 128 + 2 * cp) * 32 + dq * 8;
            const unsigned* s1 = s0 + 32;
            unsigned ov[16];
#pragma unroll
            for (int i = 0; i < 8; i++) {
                const unsigned A = s0[i], B = s1[i];
                ov[2 * i]     = __byte_perm(A, B, 0x5410);
                ov[2 * i + 1] = __byte_perm(A, B, 0x7632);
            }
            const int sz = ((cp >> 4) & 3) << 3;
            unsigned* vb = Vs + cp * 72;
#pragma unroll
            for (int grp = 0; grp < 4; grp++) {
                const int dd = (16 * dq + 4 * grp) ^ sz;
                *(uint4*)(vb + dd) =
                    make_uint4(ov[4 * grp], ov[4 * grp + 1],
                               ov[4 * grp + 2], ov[4 * grp + 3]);
            }
        }
        __syncthreads();

        // ---- S = Q K^T (raw) ----
        float4 s[16];
#pragma unroll
        for (int j = 0; j < 16; j++) s[j] = make_float4(0.f, 0.f, 0.f, 0.f);
#pragma unroll
        for (int k16 = 0; k16 < 4; k16++) {
            const unsigned* qp = Qs + (rw + g) * 36 + k16 * 8 + tq;
            unsigned a0 = qp[0], a1 = qp[8 * 36], a2 = qp[4], a3 = qp[8 * 36 + 4];
#pragma unroll
            for (int j = 0; j < 16; j++) {
                const unsigned* kp = Ks + (j * 8 + g) * 36 + k16 * 8 + tq;
                mma16(s[j], a0, a1, a2, a3, kp[0], kp[4]);
            }
        }

        // ---- online softmax, scale folded into exp args ----
        float nm0 = -1e30f, nm1 = -1e30f;
#pragma unroll
        for (int j = 0; j < 16; j++) {
            nm0 = fmaxf(nm0, fmaxf(s[j].x, s[j].y));
            nm1 = fmaxf(nm1, fmaxf(s[j].z, s[j].w));
        }
        nm0 = fmaxf(nm0, __shfl_xor_sync(0xffffffffu, nm0, 1));
        nm0 = fmaxf(nm0, __shfl_xor_sync(0xffffffffu, nm0, 2));
        nm1 = fmaxf(nm1, __shfl_xor_sync(0xffffffffu, nm1, 1));
        nm1 = fmaxf(nm1, __shfl_xor_sync(0xffffffffu, nm1, 2));
        const float mn0 = fmaxf(m0, nm0), mn1 = fmaxf(m1, nm1);
        const float cr0 = ex2(SCALE * (m0 - mn0));
        const float cr1 = ex2(SCALE * (m1 - mn1));
        m0 = mn0; m1 = mn1;
        const float nb0 = -SCALE * mn0, nb1 = -SCALE * mn1;

        unsigned pa[16], pb[16];
        float s0 = 0.f, s1 = 0.f;
#pragma unroll
        for (int j = 0; j < 16; j++) {
            float e0 = ex2(fmaf(s[j].x, SCALE, nb0));
            float e1 = ex2(fmaf(s[j].y, SCALE, nb0));
            float e2 = ex2(fmaf(s[j].z, SCALE, nb1));
            float e3 = ex2(fmaf(s[j].w, SCALE, nb1));
            s0 += e0 + e1;
            s1 += e2 + e3;
            pa[j] = h2pk(e0, e1);
            pb[j] = h2pk(e2, e3);
        }
        s0 += __shfl_xor_sync(0xffffffffu, s0, 1);
        s0 += __shfl_xor_sync(0xffffffffu, s0, 2);
        s1 += __shfl_xor_sync(0xffffffffu, s1, 1);
        s1 += __shfl_xor_sync(0xffffffffu, s1, 2);
        l0 = l0 * cr0 + s0;
        l1 = l1 * cr1 + s1;
#pragma unroll
        for (int jt = 0; jt < 8; jt++) {
            o[jt].x *= cr0; o[jt].y *= cr0;
            o[jt].z *= cr1; o[jt].w *= cr1;
        }

        // ---- O += P V ----
#pragma unroll
        for (int kc = 0; kc < 8; kc++) {
            unsigned a0 = pa[2 * kc], a1 = pb[2 * kc];
            unsigned a2 = pa[2 * kc + 1], a3 = pb[2 * kc + 1];
            const int cp0 = kc * 8 + tq, cp1 = cp0 + 4;
            const unsigned* v0 = Vs + cp0 * 72;
            const unsigned* v1 = Vs + cp1 * 72;
            const int sz0 = ((cp0 >> 4) & 3) << 3;
            const int sz1 = ((cp1 >> 4) & 3) << 3;
#pragma unroll
            for (int jt = 0; jt < 8; jt++) {
                const int d = jt * 8 + g;
                mma16(o[jt], a0, a1, a2, a3, v0[d ^ sz0], v1[d ^ sz1]);
            }
        }
    }

    // ---- epilogue: /l, fp16 out [b][n][c] ----
    const float i0 = 1.0f / l0, i1 = 1.0f / l1;
    const int b = bh >> 3, h = bh & 7;
#pragma unroll
    for (int jt = 0; jt < 8; jt++) {
        const int d0 = jt * 8 + 2 * tq;
        const size_t uidx =
            ((size_t)b * NSP + ntile + rw + g) * 256 + h * 32 + (d0 >> 1);
        g_oh[uidx]           = h2pk(o[jt].x * i0, o[jt].y * i0);
        g_oh[uidx + 8 * 256] = h2pk(o[jt].z * i1, o[jt].w * i1);
    }
}

// ---------------------------------------------------------------------------
extern "C" void kernel_launch(void* const* d_in, const int* in_sizes, int n_in,
                              void* d_out, int out_size) {
    const float* x      = (const float*)d_in[0];
    const float* w_qkv  = (const float*)d_in[1];
    const float* w_proj = (const float*)d_in[2];
    float* out = (float*)d_out;

    cudaFuncSetAttribute(hgemm_kernel<0>,
                         cudaFuncAttributeMaxDynamicSharedMemorySize, GEMM_SMEM);
    cudaFuncSetAttribute(hgemm_kernel<1>,
                         cudaFuncAttributeMaxDynamicSharedMemorySize, GEMM_SMEM);
    cudaFuncSetAttribute(attn_kernel,
                         cudaFuncAttributeMaxDynamicSharedMemorySize, ATTN_SMEM);

    f2h_kernel<<<1536, 256>>>(w_qkv, 0);
    f2h_kernel<<<512, 256>>>(w_proj, 1);
    convx_kernel<<<dim3(128, 16, 4), 256>>>(x);
    hgemm_kernel<0><<<dim3(32, 12, NB), 256, GEMM_SMEM>>>(nullptr);
    rope_kernel<<<1024, 256>>>();
    attn_kernel<<<dim3(32, 32), 256, ATTN_SMEM>>>();
    hgemm_kernel<1><<<dim3(32, 4, NB), 256, GEMM_SMEM>>>(out);
}

// round 10
// speedup vs baseline: 8.3968x; 1.2719x over previous
#include <cuda_runtime.h>
#include <cuda_fp16.h>

#define NB    4
#define CDIM  512
#define NHEAD 8
#define HD    64
#define NSP   4096
#define NBH   32

// fp16 storage, addressed as uint = half2 pair (low = even index)
__device__ unsigned g_xh[NB * NSP * 256];    // x^T  [b][n][c/2]
__device__ unsigned g_wh[1536 * 256];        // w_qkv [o][c/2]
__device__ unsigned g_wph[512 * 256];        // w_proj [o][c/2]
__device__ unsigned g_qh[NBH * NSP * 32];    // [bh][n][d/2]
__device__ unsigned g_kh[NBH * NSP * 32];
__device__ __half  g_vt[NBH * HD * NSP];     // V^T [bh][d][n]
__device__ unsigned g_oh[NB * NSP * 256];    // attn out [b][n][c/2]
__device__ float2  g_rt[64 * 16];            // rope table [pos][freq] (cos,sin)

// ---- helpers ----
__device__ __forceinline__ unsigned h2pk(float lo, float hi) {
    unsigned r; asm("cvt.rn.f16x2.f32 %0,%1,%2;" : "=r"(r) : "f"(hi), "f"(lo)); return r;
}
__device__ __forceinline__ float ex2(float x) {
    float r; asm("ex2.approx.f32 %0,%1;" : "=f"(r) : "f"(x)); return r;
}
__device__ __forceinline__ void mma16(float4& d, unsigned a0, unsigned a1,
                                      unsigned a2, unsigned a3,
                                      unsigned b0, unsigned b1) {
    asm("mma.sync.aligned.m16n8k16.row.col.f32.f16.f16.f32 "
        "{%0,%1,%2,%3},{%4,%5,%6,%7},{%8,%9},{%0,%1,%2,%3};"
        : "+f"(d.x), "+f"(d.y), "+f"(d.z), "+f"(d.w)
        : "r"(a0), "r"(a1), "r"(a2), "r"(a3), "r"(b0), "r"(b1));
}
__device__ __forceinline__ void cpa16(unsigned dst, const void* src) {
    asm volatile("cp.async.cg.shared.global [%0], [%1], 16;"
                 :: "r"(dst), "l"(src) : "memory");
}
#define CP_COMMIT() asm volatile("cp.async.commit_group;" ::: "memory")
#define CP_WAIT1()  asm volatile("cp.async.wait_group 1;" ::: "memory")

// ---------------------------------------------------------------------------
// One-time converts
// ---------------------------------------------------------------------------
__global__ void __launch_bounds__(256) f2h_kernel(const float* __restrict__ src,
                                                  int which) {
    unsigned* dst = which ? g_wph : g_wh;
    const int i = blockIdx.x * 256 + threadIdx.x;
    float2 v = ((const float2*)src)[i];
    dst[i] = h2pk(v.x, v.y);
}

__global__ void __launch_bounds__(256) convx_kernel(const float* __restrict__ x) {
    __shared__ float ts[32][33];
    const int t = threadIdx.x;
    const int n0 = blockIdx.x * 32, c0 = blockIdx.y * 32, b = blockIdx.z;
    const int tx = t & 31, ty = t >> 5;
    const float* xp = x + ((size_t)b * CDIM + c0) * NSP + n0;
#pragma unroll
    for (int i = 0; i < 4; i++)
        ts[ty + 8 * i][tx] = xp[(size_t)(ty + 8 * i) * NSP + tx];
    __syncthreads();
    const int r = t >> 4, cp = t & 15;
#pragma unroll
    for (int i = 0; i < 2; i++) {
        const int rr = r + 16 * i;
        g_xh[((size_t)b * NSP + n0 + rr) * 256 + (c0 >> 1) + cp] =
            h2pk(ts[2 * cp][rr], ts[2 * cp + 1][rr]);
    }
}

__global__ void __launch_bounds__(256) rope_tab_kernel() {
    const int idx = blockIdx.x * 256 + threadIdx.x;   // [pos][f]
    const int f = idx & 15, pos = idx >> 4;
    const float ang = (float)pos * exp2f(-0.8304820237218406f * (float)f);
    float sn, cs;
    sincosf(ang, &sn, &cs);
    g_rt[idx] = make_float2(cs, sn);
}

// ---------------------------------------------------------------------------
// fp16 tensor GEMM, 128x128 tile, KT=64, cp.async 2-stage double buffer.
// MODE 0: A = g_xh (token rows), B = g_wh; out q,k [bh][n][d] f16, v -> g_vt.
// MODE 1: A = g_wph, B = g_oh (token rows); out f32 [b][o][n].
// ---------------------------------------------------------------------------
#define GEMM_SMEM (2 * 9216 * 4)

template <int MODE>
__global__ void __launch_bounds__(256, 2) hgemm_kernel(float* __restrict__ Out) {
    extern __shared__ unsigned sm[];
    const unsigned smb = (unsigned)__cvta_generic_to_shared(sm);

    const int t    = threadIdx.x;
    const int lane = t & 31;
    const int g    = lane >> 2;
    const int tq   = lane & 3;
    const int w    = t >> 5;
    const int wr   = (w >> 2) * 64;
    const int wn   = (w & 3) * 32;

    const unsigned* Ag;
    const unsigned* Bg;
    if (MODE == 0) {
        Ag = g_xh + ((size_t)blockIdx.z * NSP + blockIdx.x * 128) * 256;
        Bg = g_wh + (size_t)blockIdx.y * 128 * 256;
    } else {
        Ag = g_wph + (size_t)blockIdx.y * 128 * 256;
        Bg = g_oh + ((size_t)blockIdx.z * NSP + blockIdx.x * 128) * 256;
    }

    const int fr = t >> 3, fc = (t & 7) * 4;

    float4 acc[4][4];
#pragma unroll
    for (int i = 0; i < 4; i++)
#pragma unroll
        for (int j = 0; j < 4; j++) acc[i][j] = make_float4(0.f, 0.f, 0.f, 0.f);

#define FILL(st, kt)                                                          \
    {                                                                         \
        _Pragma("unroll")                                                     \
        for (int i = 0; i < 4; i++) {                                         \
            const int r = fr + 32 * i;                                        \
            cpa16(smb + ((st) * 9216 + r * 36 + fc) * 4,                      \
                  Ag + (size_t)r * 256 + (kt) * 32 + fc);                     \
            cpa16(smb + ((st) * 9216 + 4608 + r * 36 + fc) * 4,               \
                  Bg + (size_t)r * 256 + (kt) * 32 + fc);                     \
        }                                                                     \
    }

    FILL(0, 0); CP_COMMIT();
    FILL(1, 1); CP_COMMIT();

    for (int kt = 0; kt < 8; kt++) {
        CP_WAIT1();
        __syncthreads();
        const unsigned* As = sm + (kt & 1) * 9216;
        const unsigned* Bs = As + 4608;
#pragma unroll
        for (int k16 = 0; k16 < 4; k16++) {
            unsigned a[4][4], b[4][2];
#pragma unroll
            for (int mt = 0; mt < 4; mt++) {
                const unsigned* p = As + (wr + mt * 16 + g) * 36 + k16 * 8 + tq;
                a[mt][0] = p[0]; a[mt][1] = p[8 * 36];
                a[mt][2] = p[4]; a[mt][3] = p[8 * 36 + 4];
            }
#pragma unroll
            for (int nt = 0; nt < 4; nt++) {
                const unsigned* p = Bs + (wn + nt * 8 + g) * 36 + k16 * 8 + tq;
                b[nt][0] = p[0]; b[nt][1] = p[4];
            }
#pragma unroll
            for (int mt = 0; mt < 4; mt++)
#pragma unroll
                for (int nt = 0; nt < 4; nt++)
                    mma16(acc[mt][nt], a[mt][0], a[mt][1], a[mt][2], a[mt][3],
                          b[nt][0], b[nt][1]);
        }
        __syncthreads();
        if (kt + 2 < 8) FILL(kt & 1, kt + 2);
        CP_COMMIT();
    }
#undef FILL

    // epilogue
#pragma unroll
    for (int mt = 0; mt < 4; mt++) {
#pragma unroll
        for (int nt = 0; nt < 4; nt++) {
            const float4 c = acc[mt][nt];
            if (MODE == 0) {
                const int o = blockIdx.y * 128 + wn + nt * 8 + 2 * tq;
                const int n = blockIdx.x * 128 + wr + mt * 16 + g;
                const int s = o >> 9, h = (o >> 6) & 7, d = o & 63;
                if (s < 2) {
                    unsigned* dst = (s == 0) ? g_qh : g_kh;
                    const size_t base =
                        ((size_t)(blockIdx.z * NHEAD + h) * NSP + n) * 32 + (d >> 1);
                    dst[base]       = h2pk(c.x, c.y);
                    dst[base + 256] = h2pk(c.z, c.w);   // n+8
                } else {
                    __half* vt = g_vt +
                        ((size_t)(blockIdx.z * NHEAD + h) * HD + d) * NSP + n;
                    vt[0]        = __float2half(c.x);
                    vt[NSP]      = __float2half(c.y);   // d+1
                    vt[8]        = __float2half(c.z);   // n+8
                    vt[NSP + 8]  = __float2half(c.w);
                }
            } else {
                const int o = blockIdx.y * 128 + wr + mt * 16 + g;
                const int n = blockIdx.x * 128 + wn + nt * 8 + 2 * tq;
                const size_t base = ((size_t)blockIdx.z * CDIM + o) * NSP + n;
                *(float2*)&Out[base]           = make_float2(c.x, c.y);
                *(float2*)&Out[base + 8 * NSP] = make_float2(c.z, c.w);
            }
        }
    }
}

// ---------------------------------------------------------------------------
// RoPE in place on fp16 q,k [bh][n][d]; table-driven.
// ---------------------------------------------------------------------------
__global__ void __launch_bounds__(256) rope_kernel() {
    const int idx = blockIdx.x * 256 + threadIdx.x;
    const int seg = idx & 1;
    const int n   = (idx >> 1) & (NSP - 1);
    const int bh  = idx >> 13;

    const int pos = seg ? (n & 63) : (n >> 6);
    const float2* tab = g_rt + pos * 16;
    const size_t base = ((size_t)bh * NSP + n) * 32;
    unsigned* qp = g_qh + base + 8 * seg;
    unsigned* kp = g_kh + base + 8 * seg;

#pragma unroll
    for (int i = 0; i < 8; i++) {
        const float2 cs0 = tab[2 * i];
        const float2 cs1 = tab[2 * i + 1];

        float2 ql = __half22float2(*(__half2*)&qp[i]);
        float2 qh = __half22float2(*(__half2*)&qp[i + 16]);
        qp[i]      = h2pk(ql.x * cs0.x - qh.x * cs0.y, ql.y * cs1.x - qh.y * cs1.y);
        qp[i + 16] = h2pk(ql.x * cs0.y + qh.x * cs0.x, ql.y * cs1.y + qh.y * cs1.x);

        float2 kl = __half22float2(*(__half2*)&kp[i]);
        float2 kh = __half22float2(*(__half2*)&kp[i + 16]);
        kp[i]      = h2pk(kl.x * cs0.x - kh.x * cs0.y, kl.y * cs1.x - kh.y * cs1.y);
        kp[i + 16] = h2pk(kl.x * cs0.y + kh.x * cs0.x, kl.y * cs1.y + kh.y * cs1.x);
    }
}

// ---------------------------------------------------------------------------
// Flash attention, split-c. BR=128, BC=128, 8 warps:
//   warp w: row strip s = w>>1 (32 rows), column half j = w&1 (64 cols).
// Per-warp online softmax on its half; final merge via smem.
// Smem (uints): Qs 128x36 @0, K[2] 128x36 @4608+s*4608, Vt[2] 64x68 @13824+s*4352.
// K,V double-buffered via cp.async.
// ---------------------------------------------------------------------------
#define ATTN_SMEM (22528 * 4)   // 90112 B
#define SCALE 0.18033688011112042f   // hd^-1/2 * log2(e)

__global__ void __launch_bounds__(256, 1) attn_kernel() {
    extern __shared__ unsigned smu[];
    unsigned* Qs = smu;
    const unsigned smb = (unsigned)__cvta_generic_to_shared(smu);

    const int t    = threadIdx.x;
    const int lane = t & 31;
    const int g    = lane >> 2;
    const int tq   = lane & 3;
    const int w    = t >> 5;
    const int rb   = (w >> 1) * 32;   // row strip base
    const int jj   = w & 1;           // column half
    const int bh   = blockIdx.y;
    const int ntile = blockIdx.x * 128;

    const unsigned* Qg  = g_qh + ((size_t)bh * NSP + ntile) * 32;
    const unsigned* Kg  = g_kh + (size_t)bh * NSP * 32;
    const unsigned* Vtg = (const unsigned*)g_vt + (size_t)bh * HD * 2048;

    // Q fill (plain stores, once)
    {
        const int r = t >> 1, sg = (t & 1) * 16;
        const uint4* src = (const uint4*)(Qg + (size_t)r * 32 + sg);
        uint4* dst = (uint4*)(Qs + r * 36 + sg);
        dst[0] = src[0]; dst[1] = src[1]; dst[2] = src[2]; dst[3] = src[3];
    }

#define AFILL(kt, st)                                                         \
    {                                                                         \
        _Pragma("unroll")                                                     \
        for (int i = 0; i < 4; i++) {                                         \
            const int id = t + 256 * i;                                       \
            const int r = id >> 3, ch = (id & 7) * 4;                         \
            cpa16(smb + (4608 + (st) * 4608 + r * 36 + ch) * 4,               \
                  Kg + (size_t)((kt) * 128 + r) * 32 + ch);                   \
        }                                                                     \
        _Pragma("unroll")                                                     \
        for (int i = 0; i < 4; i++) {                                         \
            const int id = t + 256 * i;                                       \
            const int d = id >> 4, ch = (id & 15) * 4;                        \
            cpa16(smb + (13824 + (st) * 4352 + d * 68 + ch) * 4,              \
                  Vtg + (size_t)d * 2048 + (kt) * 64 + ch);                   \
        }                                                                     \
    }

    AFILL(0, 0); CP_COMMIT();
    AFILL(1, 1); CP_COMMIT();

    float4 oa[2][8];
#pragma unroll
    for (int mt = 0; mt < 2; mt++)
#pragma unroll
        for (int n8 = 0; n8 < 8; n8++) oa[mt][n8] = make_float4(0.f, 0.f, 0.f, 0.f);
    float mrow[2][2], lrow[2][2];
#pragma unroll
    for (int mt = 0; mt < 2; mt++) {
        mrow[mt][0] = -1e30f; mrow[mt][1] = -1e30f;
        lrow[mt][0] = 0.f;    lrow[mt][1] = 0.f;
    }

    for (int kt = 0; kt < 32; kt++) {
        CP_WAIT1();
        __syncthreads();
        const unsigned* Ks = smu + 4608 + (kt & 1) * 4608;
        const unsigned* Vt = smu + 13824 + (kt & 1) * 4352;

        // ---- S = Q K^T (warp's 32 rows x 64 cols) ----
        float4 sa[2][8];
#pragma unroll
        for (int mt = 0; mt < 2; mt++)
#pragma unroll
            for (int n8 = 0; n8 < 8; n8++) sa[mt][n8] = make_float4(0.f, 0.f, 0.f, 0.f);
#pragma unroll
        for (int k16 = 0; k16 < 4; k16++) {
            unsigned a[2][4];
#pragma unroll
            for (int mt = 0; mt < 2; mt++) {
                const unsigned* p = Qs + (rb + mt * 16 + g) * 36 + k16 * 8 + tq;
                a[mt][0] = p[0]; a[mt][1] = p[8 * 36];
                a[mt][2] = p[4]; a[mt][3] = p[8 * 36 + 4];
            }
#pragma unroll
            for (int n8 = 0; n8 < 8; n8++) {
                const unsigned* kp = Ks + (64 * jj + n8 * 8 + g) * 36 + k16 * 8 + tq;
                const unsigned b0 = kp[0], b1 = kp[4];
                mma16(sa[0][n8], a[0][0], a[0][1], a[0][2], a[0][3], b0, b1);
                mma16(sa[1][n8], a[1][0], a[1][1], a[1][2], a[1][3], b0, b1);
            }
        }

        // ---- online softmax per mt ----
        unsigned pa[2][8], pb[2][8];
#pragma unroll
        for (int mt = 0; mt < 2; mt++) {
            float nm0 = -1e30f, nm1 = -1e30f;
#pragma unroll
            for (int n8 = 0; n8 < 8; n8++) {
                nm0 = fmaxf(nm0, fmaxf(sa[mt][n8].x, sa[mt][n8].y));
                nm1 = fmaxf(nm1, fmaxf(sa[mt][n8].z, sa[mt][n8].w));
            }
            nm0 = fmaxf(nm0, __shfl_xor_sync(0xffffffffu, nm0, 1));
            nm0 = fmaxf(nm0, __shfl_xor_sync(0xffffffffu, nm0, 2));
            nm1 = fmaxf(nm1, __shfl_xor_sync(0xffffffffu, nm1, 1));
            nm1 = fmaxf(nm1, __shfl_xor_sync(0xffffffffu, nm1, 2));
            const float mn0 = fmaxf(mrow[mt][0], nm0);
            const float mn1 = fmaxf(mrow[mt][1], nm1);
            const float cr0 = ex2(SCALE * (mrow[mt][0] - mn0));
            const float cr1 = ex2(SCALE * (mrow[mt][1] - mn1));
            mrow[mt][0] = mn0; mrow[mt][1] = mn1;
            const float nb0 = -SCALE * mn0, nb1 = -SCALE * mn1;
            float s0 = 0.f, s1 = 0.f;
#pragma unroll
            for (int n8 = 0; n8 < 8; n8++) {
                float e0 = ex2(fmaf(sa[mt][n8].x, SCALE, nb0));
                float e1 = ex2(fmaf(sa[mt][n8].y, SCALE, nb0));
                float e2 = ex2(fmaf(sa[mt][n8].z, SCALE, nb1));
                float e3 = ex2(fmaf(sa[mt][n8].w, SCALE, nb1));
                s0 += e0 + e1; s1 += e2 + e3;
                pa[mt][n8] = h2pk(e0, e1);
                pb[mt][n8] = h2pk(e2, e3);
            }
            s0 += __shfl_xor_sync(0xffffffffu, s0, 1);
            s0 += __shfl_xor_sync(0xffffffffu, s0, 2);
            s1 += __shfl_xor_sync(0xffffffffu, s1, 1);
            s1 += __shfl_xor_sync(0xffffffffu, s1, 2);
            lrow[mt][0] = lrow[mt][0] * cr0 + s0;
            lrow[mt][1] = lrow[mt][1] * cr1 + s1;
#pragma unroll
            for (int n8 = 0; n8 < 8; n8++) {
                oa[mt][n8].x *= cr0; oa[mt][n8].y *= cr0;
                oa[mt][n8].z *= cr1; oa[mt][n8].w *= cr1;
            }
        }

        // ---- O += P V (B from V^T tile, warp's c-half) ----
#pragma unroll
        for (int kc = 0; kc < 4; kc++) {
#pragma unroll
            for (int n8 = 0; n8 < 8; n8++) {
                const unsigned* vp = Vt + (n8 * 8 + g) * 68 + 32 * jj + kc * 8 + tq;
                const unsigned b0 = vp[0], b1 = vp[4];
                mma16(oa[0][n8], pa[0][2 * kc], pb[0][2 * kc],
                      pa[0][2 * kc + 1], pb[0][2 * kc + 1], b0, b1);
                mma16(oa[1][n8], pa[1][2 * kc], pb[1][2 * kc],
                      pa[1][2 * kc + 1], pb[1][2 * kc + 1], b0, b1);
            }
        }

        __syncthreads();
        if (kt + 2 < 32) AFILL(kt + 2, kt & 1);
        CP_COMMIT();
    }
#undef AFILL

    // ---- merge halves: j=1 publishes, j=0 combines & stores ----
    __syncthreads();
    float* smf  = (float*)smu;          // O1: 128 x 66
    float* smm  = smf + 8448;           // m1[128]
    float* sml  = smf + 8576;           // l1[128]

    if (jj == 1) {
#pragma unroll
        for (int mt = 0; mt < 2; mt++) {
            const int r0 = rb + mt * 16 + g;
            if (tq == 0) {
                smm[r0]     = mrow[mt][0];  sml[r0]     = lrow[mt][0];
                smm[r0 + 8] = mrow[mt][1];  sml[r0 + 8] = lrow[mt][1];
            }
#pragma unroll
            for (int n8 = 0; n8 < 8; n8++) {
                *(float2*)&smf[r0 * 66 + n8 * 8 + 2 * tq] =
                    make_float2(oa[mt][n8].x, oa[mt][n8].y);
                *(float2*)&smf[(r0 + 8) * 66 + n8 * 8 + 2 * tq] =
                    make_float2(oa[mt][n8].z, oa[mt][n8].w);
            }
        }
    }
    __syncthreads();
    if (jj == 0) {
        const int b = bh >> 3, h_ = bh & 7;
#pragma unroll
        for (int mt = 0; mt < 2; mt++) {
#pragma unroll
            for (int hh = 0; hh < 2; hh++) {
                const int r = rb + mt * 16 + g + 8 * hh;
                const float m1 = smm[r], l1 = sml[r];
                const float m0v = mrow[mt][hh], l0v = lrow[mt][hh];
                const float mm = fmaxf(m0v, m1);
                const float c0 = ex2(SCALE * (m0v - mm));
                const float c1 = ex2(SCALE * (m1 - mm));
                const float inv = 1.0f / (l0v * c0 + l1 * c1);
                const size_t ub =
                    ((size_t)b * NSP + ntile + r) * 256 + h_ * 32;
#pragma unroll
                for (int n8 = 0; n8 < 8; n8++) {
                    const float2 o1 = *(float2*)&smf[r * 66 + n8 * 8 + 2 * tq];
                    const float fx = hh ? oa[mt][n8].z : oa[mt][n8].x;
                    const float fy = hh ? oa[mt][n8].w : oa[mt][n8].y;
                    g_oh[ub + n8 * 4 + tq] =
                        h2pk((fx * c0 + o1.x * c1) * inv,
                             (fy * c0 + o1.y * c1) * inv);
                }
            }
        }
    }
}

// ---------------------------------------------------------------------------
extern "C" void kernel_launch(void* const* d_in, const int* in_sizes, int n_in,
                              void* d_out, int out_size) {
    const float* x      = (const float*)d_in[0];
    const float* w_qkv  = (const float*)d_in[1];
    const float* w_proj = (const float*)d_in[2];
    float* out = (float*)d_out;

    cudaFuncSetAttribute(hgemm_kernel<0>,
                         cudaFuncAttributeMaxDynamicSharedMemorySize, GEMM_SMEM);
    cudaFuncSetAttribute(hgemm_kernel<1>,
                         cudaFuncAttributeMaxDynamicSharedMemorySize, GEMM_SMEM);
    cudaFuncSetAttribute(attn_kernel,
                         cudaFuncAttributeMaxDynamicSharedMemorySize, ATTN_SMEM);

    f2h_kernel<<<1536, 256>>>(w_qkv, 0);
    f2h_kernel<<<512, 256>>>(w_proj, 1);
    convx_kernel<<<dim3(128, 16, 4), 256>>>(x);
    rope_tab_kernel<<<4, 256>>>();
    hgemm_kernel<0><<<dim3(32, 12, NB), 256, GEMM_SMEM>>>(nullptr);
    rope_kernel<<<1024, 256>>>();
    attn_kernel<<<dim3(32, 32), 256, ATTN_SMEM>>>();
    hgemm_kernel<1><<<dim3(32, 4, NB), 256, GEMM_SMEM>>>(out);
}

// round 11
// speedup vs baseline: 8.8203x; 1.0504x over previous
#include <cuda_runtime.h>
#include <cuda_fp16.h>

#define NB    4
#define CDIM  512
#define NHEAD 8
#define HD    64
#define NSP   4096
#define NBH   32

// fp16 storage, addressed as uint = half2 pair (low = even index)
__device__ unsigned g_xh[NB * NSP * 256];    // x^T  [b][n][c/2]
__device__ unsigned g_wh[1536 * 256];        // w_qkv [o][c/2]
__device__ unsigned g_wph[512 * 256];        // w_proj [o][c/2]
__device__ unsigned g_qh[NBH * NSP * 32];    // [bh][n][d/2]  (roped)
__device__ unsigned g_kh[NBH * NSP * 32];
__device__ unsigned g_vt[NBH * HD * 2048];   // V^T [bh][d][n/2]
__device__ unsigned g_oh[NB * NSP * 256];    // attn out [b][n][c/2]
__device__ float2  g_rt[64 * 16];            // rope table [pos][freq] (cos,sin)

// ---- helpers ----
__device__ __forceinline__ unsigned h2pk(float lo, float hi) {
    unsigned r; asm("cvt.rn.f16x2.f32 %0,%1,%2;" : "=r"(r) : "f"(hi), "f"(lo)); return r;
}
__device__ __forceinline__ float ex2(float x) {
    float r; asm("ex2.approx.f32 %0,%1;" : "=f"(r) : "f"(x)); return r;
}
__device__ __forceinline__ void mma16(float4& d, unsigned a0, unsigned a1,
                                      unsigned a2, unsigned a3,
                                      unsigned b0, unsigned b1) {
    asm("mma.sync.aligned.m16n8k16.row.col.f32.f16.f16.f32 "
        "{%0,%1,%2,%3},{%4,%5,%6,%7},{%8,%9},{%0,%1,%2,%3};"
        : "+f"(d.x), "+f"(d.y), "+f"(d.z), "+f"(d.w)
        : "r"(a0), "r"(a1), "r"(a2), "r"(a3), "r"(b0), "r"(b1));
}
__device__ __forceinline__ void ldsm4(uint4& v, unsigned a) {
    asm volatile("ldmatrix.sync.aligned.m8n8.x4.shared.b16 {%0,%1,%2,%3},[%4];"
                 : "=r"(v.x), "=r"(v.y), "=r"(v.z), "=r"(v.w) : "r"(a));
}
__device__ __forceinline__ void cpa16(unsigned dst, const void* src) {
    asm volatile("cp.async.cg.shared.global [%0], [%1], 16;"
                 :: "r"(dst), "l"(src) : "memory");
}
#define CP_COMMIT() asm volatile("cp.async.commit_group;" ::: "memory")
#define CP_WAIT1()  asm volatile("cp.async.wait_group 1;" ::: "memory")

// ---------------------------------------------------------------------------
// One-time converts
// ---------------------------------------------------------------------------
__global__ void __launch_bounds__(256) f2h_kernel(const float* __restrict__ src,
                                                  int which) {
    unsigned* dst = which ? g_wph : g_wh;
    const int i = blockIdx.x * 256 + threadIdx.x;
    float2 v = ((const float2*)src)[i];
    dst[i] = h2pk(v.x, v.y);
}

__global__ void __launch_bounds__(256) convx_kernel(const float* __restrict__ x) {
    __shared__ float ts[32][33];
    const int t = threadIdx.x;
    const int n0 = blockIdx.x * 32, c0 = blockIdx.y * 32, b = blockIdx.z;
    const int tx = t & 31, ty = t >> 5;
    const float* xp = x + ((size_t)b * CDIM + c0) * NSP + n0;
#pragma unroll
    for (int i = 0; i < 4; i++)
        ts[ty + 8 * i][tx] = xp[(size_t)(ty + 8 * i) * NSP + tx];
    __syncthreads();
    const int r = t >> 4, cp = t & 15;
#pragma unroll
    for (int i = 0; i < 2; i++) {
        const int rr = r + 16 * i;
        g_xh[((size_t)b * NSP + n0 + rr) * 256 + (c0 >> 1) + cp] =
            h2pk(ts[2 * cp][rr], ts[2 * cp + 1][rr]);
    }
}

__global__ void __launch_bounds__(256) rope_tab_kernel() {
    const int idx = blockIdx.x * 256 + threadIdx.x;   // [pos][f]
    const int f = idx & 15, pos = idx >> 4;
    const float ang = (float)pos * exp2f(-0.8304820237218406f * (float)f);
    float sn, cs;
    sincosf(ang, &sn, &cs);
    g_rt[idx] = make_float2(cs, sn);
}

// ---------------------------------------------------------------------------
// fp16 tensor GEMM, 128x128 tile, KT=64, cp.async double buffer, ldmatrix.
// MODE 0:
//   by<8  (q,k): A = tokens, B = w; epilogue stages [n][o] in smem, applies
//                RoPE from g_rt, writes fp16 [bh][n][d].
//   by>=8 (v):   A = w, B = tokens; frags hold adjacent n -> direct V^T store.
// MODE 1: A = w_proj, B = g_oh; out f32 [b][o][n].
// ---------------------------------------------------------------------------
#define GEMM_SMEM (2 * 9216 * 4)

template <int MODE>
__global__ void __launch_bounds__(256, 2) hgemm_kernel(float* __restrict__ Out) {
    extern __shared__ unsigned sm[];
    const unsigned smb = (unsigned)__cvta_generic_to_shared(sm);

    const int t    = threadIdx.x;
    const int lane = t & 31;
    const int g    = lane >> 2;
    const int tq   = lane & 3;
    const int w    = t >> 5;
    const int wr   = (w >> 2) * 64;
    const int wn   = (w & 3) * 32;
    const bool vblk = (MODE == 0) && (blockIdx.y >= 8);

    const unsigned* Ag;
    const unsigned* Bg;
    if (MODE == 0) {
        const unsigned* tok = g_xh + ((size_t)blockIdx.z * NSP + blockIdx.x * 128) * 256;
        const unsigned* wgt = g_wh + (size_t)blockIdx.y * 128 * 256;
        Ag = vblk ? wgt : tok;
        Bg = vblk ? tok : wgt;
    } else {
        Ag = g_wph + (size_t)blockIdx.y * 128 * 256;
        Bg = g_oh + ((size_t)blockIdx.z * NSP + blockIdx.x * 128) * 256;
    }

    const int fr = t >> 3, fc = (t & 7) * 4;
    const int lrow = lane & 15;
    const int lcolb = (lane >> 4) * 16;
    const unsigned ab = smb + (wr + lrow) * 144 + lcolb;
    const unsigned bb = smb + 18432 + (wn + lrow) * 144 + lcolb;

    float4 acc[4][4];
#pragma unroll
    for (int i = 0; i < 4; i++)
#pragma unroll
        for (int j = 0; j < 4; j++) acc[i][j] = make_float4(0.f, 0.f, 0.f, 0.f);

#define FILL(st, kt)                                                          \
    {                                                                         \
        _Pragma("unroll")                                                     \
        for (int i = 0; i < 4; i++) {                                         \
            const int r = fr + 32 * i;                                        \
            cpa16(smb + ((st) * 9216 + r * 36 + fc) * 4,                      \
                  Ag + (size_t)r * 256 + (kt) * 32 + fc);                     \
            cpa16(smb + ((st) * 9216 + 4608 + r * 36 + fc) * 4,               \
                  Bg + (size_t)r * 256 + (kt) * 32 + fc);                     \
        }                                                                     \
    }

    FILL(0, 0); CP_COMMIT();
    FILL(1, 1); CP_COMMIT();

    for (int kt = 0; kt < 8; kt++) {
        CP_WAIT1();
        __syncthreads();
        const unsigned stoff = (kt & 1) * 36864;
#pragma unroll
        for (int k16 = 0; k16 < 4; k16++) {
            uint4 av[4], bv[2];
#pragma unroll
            for (int mt = 0; mt < 4; mt++)
                ldsm4(av[mt], ab + stoff + mt * 2304 + k16 * 32);
#pragma unroll
            for (int p = 0; p < 2; p++)
                ldsm4(bv[p], bb + stoff + p * 2304 + k16 * 32);
#pragma unroll
            for (int mt = 0; mt < 4; mt++)
#pragma unroll
                for (int nt = 0; nt < 4; nt++) {
                    const uint4& b4 = bv[nt >> 1];
                    const unsigned b0 = (nt & 1) ? b4.y : b4.x;
                    const unsigned b1 = (nt & 1) ? b4.w : b4.z;
                    mma16(acc[mt][nt], av[mt].x, av[mt].y, av[mt].z, av[mt].w,
                          b0, b1);
                }
        }
        __syncthreads();
        if (kt + 2 < 8) FILL(kt & 1, kt + 2);
        CP_COMMIT();
    }
#undef FILL

    // ---- epilogues ----
    if (MODE == 1) {
#pragma unroll
        for (int mt = 0; mt < 4; mt++)
#pragma unroll
            for (int nt = 0; nt < 4; nt++) {
                const float4 c = acc[mt][nt];
                const int o = blockIdx.y * 128 + wr + mt * 16 + g;
                const int n = blockIdx.x * 128 + wn + nt * 8 + 2 * tq;
                const size_t base = ((size_t)blockIdx.z * CDIM + o) * NSP + n;
                *(float2*)&Out[base]           = make_float2(c.x, c.y);
                *(float2*)&Out[base + 8 * NSP] = make_float2(c.z, c.w);
            }
        return;
    }

    if (vblk) {
        // rows = o (d), cols = n : direct coalesced V^T store
        const int hv = (blockIdx.y & 3) << 1;
#pragma unroll
        for (int mt = 0; mt < 4; mt++)
#pragma unroll
            for (int nt = 0; nt < 4; nt++) {
                const float4 c = acc[mt][nt];
                const int ol = wr + mt * 16 + g;
                const int h  = hv + (ol >> 6);
                const int d  = ol & 63;
                const int nn = blockIdx.x * 128 + wn + nt * 8 + 2 * tq;
                const size_t base =
                    ((size_t)(blockIdx.z * NHEAD + h) * HD + d) * 2048 + (nn >> 1);
                g_vt[base]            = h2pk(c.x, c.y);
                g_vt[base + 8 * 2048] = h2pk(c.z, c.w);   // d+8
            }
        return;
    }

    // q/k: stage fp32 tile [n][o] (stride 132), then RoPE + fp16 store
    float* smf = (float*)sm;
#pragma unroll
    for (int mt = 0; mt < 4; mt++)
#pragma unroll
        for (int nt = 0; nt < 4; nt++) {
            const float4 c = acc[mt][nt];
            const int n  = wr + mt * 16 + g;
            const int ol = wn + nt * 8 + 2 * tq;
            smf[n * 132 + ol]           = c.x;
            smf[n * 132 + ol + 1]       = c.y;
            smf[(n + 8) * 132 + ol]     = c.z;
            smf[(n + 8) * 132 + ol + 1] = c.w;
        }
    __syncthreads();

    {
        unsigned* dst = (blockIdx.y >> 2) ? g_kh : g_qh;
        const int dp = t & 15, hp = (t >> 4) & 1, nw = t >> 5;
        const int h  = ((blockIdx.y & 3) << 1) + hp;
        const int f0 = (dp < 8) ? 2 * dp : 2 * dp - 16;
        const size_t bhb = (size_t)(blockIdx.z * NHEAD + h) * NSP;
#pragma unroll
        for (int i = 0; i < 16; i++) {
            const int n  = nw * 16 + i;
            const int gn = blockIdx.x * 128 + n;
            const int pos = (dp < 8) ? (gn >> 6) : (gn & 63);
            const float2 cs0 = g_rt[pos * 16 + f0];
            const float2 cs1 = g_rt[pos * 16 + f0 + 1];
            const float* row = smf + n * 132 + hp * 64;
            const float a1 = row[2 * dp],      a2 = row[2 * dp + 1];
            const float b1 = row[2 * dp + 32], b2 = row[2 * dp + 33];
            const size_t ub = (bhb + gn) * 32;
            dst[ub + dp]      = h2pk(a1 * cs0.x - b1 * cs0.y,
                                     a2 * cs1.x - b2 * cs1.y);
            dst[ub + 16 + dp] = h2pk(a1 * cs0.y + b1 * cs0.x,
                                     a2 * cs1.y + b2 * cs1.x);
        }
    }
}

// ---------------------------------------------------------------------------
// Flash attention, split-c, ldmatrix fragment loads. BR=128, BC=128, 8 warps:
//   warp w: row strip (w>>1)*32, column half jj = w&1.
// Smem (uints): Qs 128x36 @0, K[2] 128x36 @4608+st*4608, Vt[2] 64x68 @13824+st*4352.
// ---------------------------------------------------------------------------
#define ATTN_SMEM (22528 * 4)
#define SCALE 0.18033688011112042f   // hd^-1/2 * log2(e)

__global__ void __launch_bounds__(256, 1) attn_kernel() {
    extern __shared__ unsigned smu[];
    unsigned* Qs = smu;
    const unsigned smb = (unsigned)__cvta_generic_to_shared(smu);

    const int t    = threadIdx.x;
    const int lane = t & 31;
    const int g    = lane >> 2;
    const int tq   = lane & 3;
    const int w    = t >> 5;
    const int rb   = (w >> 1) * 32;
    const int jj   = w & 1;
    const int bh   = blockIdx.y;
    const int ntile = blockIdx.x * 128;

    const unsigned* Qg  = g_qh + ((size_t)bh * NSP + ntile) * 32;
    const unsigned* Kg  = g_kh + (size_t)bh * NSP * 32;
    const unsigned* Vtg = g_vt + (size_t)bh * HD * 2048;

    const int lrow = lane & 15;
    const int lcolb = (lane >> 4) * 16;
    const unsigned qa = smb + (rb + lrow) * 144 + lcolb;
    const unsigned ka = smb + (64 * jj + lrow) * 144 + lcolb;
    const unsigned va = smb + lrow * 272 + jj * 128 + lcolb;

    // Q fill
    {
        const int r = t >> 1, sg = (t & 1) * 16;
        const uint4* src = (const uint4*)(Qg + (size_t)r * 32 + sg);
        uint4* dst = (uint4*)(Qs + r * 36 + sg);
        dst[0] = src[0]; dst[1] = src[1]; dst[2] = src[2]; dst[3] = src[3];
    }

#define AFILL(kt, st)                                                         \
    {                                                                         \
        _Pragma("unroll")                                                     \
        for (int i = 0; i < 4; i++) {                                         \
            const int id = t + 256 * i;                                       \
            const int r = id >> 3, ch = (id & 7) * 4;                         \
            cpa16(smb + (4608 + (st) * 4608 + r * 36 + ch) * 4,               \
                  Kg + (size_t)((kt) * 128 + r) * 32 + ch);                   \
        }                                                                     \
        _Pragma("unroll")                                                     \
        for (int i = 0; i < 4; i++) {                                         \
            const int id = t + 256 * i;                                       \
            const int d = id >> 4, ch = (id & 15) * 4;                        \
            cpa16(smb + (13824 + (st) * 4352 + d * 68 + ch) * 4,              \
                  Vtg + (size_t)d * 2048 + (kt) * 64 + ch);                   \
        }                                                                     \
    }

    AFILL(0, 0); CP_COMMIT();
    AFILL(1, 1); CP_COMMIT();

    float4 oa[2][8];
#pragma unroll
    for (int mt = 0; mt < 2; mt++)
#pragma unroll
        for (int n8 = 0; n8 < 8; n8++) oa[mt][n8] = make_float4(0.f, 0.f, 0.f, 0.f);
    float mrow[2][2], lrow2[2][2];
#pragma unroll
    for (int mt = 0; mt < 2; mt++) {
        mrow[mt][0] = -1e30f; mrow[mt][1] = -1e30f;
        lrow2[mt][0] = 0.f;   lrow2[mt][1] = 0.f;
    }

    for (int kt = 0; kt < 32; kt++) {
        CP_WAIT1();
        __syncthreads();
        const unsigned kbase = ka + 18432 + (kt & 1) * 18432;
        const unsigned vbase = va + 55296 + (kt & 1) * 17408;

        // ---- S = Q K^T ----
        float4 sa[2][8];
#pragma unroll
        for (int mt = 0; mt < 2; mt++)
#pragma unroll
            for (int n8 = 0; n8 < 8; n8++) sa[mt][n8] = make_float4(0.f, 0.f, 0.f, 0.f);
#pragma unroll
        for (int k16 = 0; k16 < 4; k16++) {
            uint4 a0v, a1v, bk[4];
            ldsm4(a0v, qa + k16 * 32);
            ldsm4(a1v, qa + 2304 + k16 * 32);
#pragma unroll
            for (int p = 0; p < 4; p++)
                ldsm4(bk[p], kbase + p * 2304 + k16 * 32);
#pragma unroll
            for (int p = 0; p < 4; p++) {
                mma16(sa[0][2 * p],     a0v.x, a0v.y, a0v.z, a0v.w, bk[p].x, bk[p].z);
                mma16(sa[0][2 * p + 1], a0v.x, a0v.y, a0v.z, a0v.w, bk[p].y, bk[p].w);
                mma16(sa[1][2 * p],     a1v.x, a1v.y, a1v.z, a1v.w, bk[p].x, bk[p].z);
                mma16(sa[1][2 * p + 1], a1v.x, a1v.y, a1v.z, a1v.w, bk[p].y, bk[p].w);
            }
        }

        // ---- online softmax per mt ----
        unsigned pa[2][8], pb[2][8];
#pragma unroll
        for (int mt = 0; mt < 2; mt++) {
            float nm0 = -1e30f, nm1 = -1e30f;
#pragma unroll
            for (int n8 = 0; n8 < 8; n8++) {
                nm0 = fmaxf(nm0, fmaxf(sa[mt][n8].x, sa[mt][n8].y));
                nm1 = fmaxf(nm1, fmaxf(sa[mt][n8].z, sa[mt][n8].w));
            }
            nm0 = fmaxf(nm0, __shfl_xor_sync(0xffffffffu, nm0, 1));
            nm0 = fmaxf(nm0, __shfl_xor_sync(0xffffffffu, nm0, 2));
            nm1 = fmaxf(nm1, __shfl_xor_sync(0xffffffffu, nm1, 1));
            nm1 = fmaxf(nm1, __shfl_xor_sync(0xffffffffu, nm1, 2));
            const float mn0 = fmaxf(mrow[mt][0], nm0);
            const float mn1 = fmaxf(mrow[mt][1], nm1);
            const float cr0 = ex2(SCALE * (mrow[mt][0] - mn0));
            const float cr1 = ex2(SCALE * (mrow[mt][1] - mn1));
            mrow[mt][0] = mn0; mrow[mt][1] = mn1;
            const float nb0 = -SCALE * mn0, nb1 = -SCALE * mn1;
            float s0 = 0.f, s1 = 0.f;
#pragma unroll
            for (int n8 = 0; n8 < 8; n8++) {
                float e0 = ex2(fmaf(sa[mt][n8].x, SCALE, nb0));
                float e1 = ex2(fmaf(sa[mt][n8].y, SCALE, nb0));
                float e2 = ex2(fmaf(sa[mt][n8].z, SCALE, nb1));
                float e3 = ex2(fmaf(sa[mt][n8].w, SCALE, nb1));
                s0 += e0 + e1; s1 += e2 + e3;
                pa[mt][n8] = h2pk(e0, e1);
                pb[mt][n8] = h2pk(e2, e3);
            }
            s0 += __shfl_xor_sync(0xffffffffu, s0, 1);
            s0 += __shfl_xor_sync(0xffffffffu, s0, 2);
            s1 += __shfl_xor_sync(0xffffffffu, s1, 1);
            s1 += __shfl_xor_sync(0xffffffffu, s1, 2);
            lrow2[mt][0] = lrow2[mt][0] * cr0 + s0;
            lrow2[mt][1] = lrow2[mt][1] * cr1 + s1;
#pragma unroll
            for (int n8 = 0; n8 < 8; n8++) {
                oa[mt][n8].x *= cr0; oa[mt][n8].y *= cr0;
                oa[mt][n8].z *= cr1; oa[mt][n8].w *= cr1;
            }
        }

        // ---- O += P V ----
#pragma unroll
        for (int kc = 0; kc < 4; kc++) {
            uint4 bv[4];
#pragma unroll
            for (int p = 0; p < 4; p++)
                ldsm4(bv[p], vbase + p * 4352 + kc * 32);
#pragma unroll
            for (int p = 0; p < 4; p++) {
                mma16(oa[0][2 * p],     pa[0][2 * kc], pb[0][2 * kc],
                      pa[0][2 * kc + 1], pb[0][2 * kc + 1], bv[p].x, bv[p].z);
                mma16(oa[0][2 * p + 1], pa[0][2 * kc], pb[0][2 * kc],
                      pa[0][2 * kc + 1], pb[0][2 * kc + 1], bv[p].y, bv[p].w);
                mma16(oa[1][2 * p],     pa[1][2 * kc], pb[1][2 * kc],
                      pa[1][2 * kc + 1], pb[1][2 * kc + 1], bv[p].x, bv[p].z);
                mma16(oa[1][2 * p + 1], pa[1][2 * kc], pb[1][2 * kc],
                      pa[1][2 * kc + 1], pb[1][2 * kc + 1], bv[p].y, bv[p].w);
            }
        }

        __syncthreads();
        if (kt + 2 < 32) AFILL(kt + 2, kt & 1);
        CP_COMMIT();
    }
#undef AFILL

    // ---- merge halves: jj=1 publishes, jj=0 combines & stores ----
    __syncthreads();
    float* smf  = (float*)smu;          // O1: 128 x 66
    float* smm  = smf + 8448;
    float* sml  = smf + 8576;

    if (jj == 1) {
#pragma unroll
        for (int mt = 0; mt < 2; mt++) {
            const int r0 = rb + mt * 16 + g;
            if (tq == 0) {
                smm[r0]     = mrow[mt][0];  sml[r0]     = lrow2[mt][0];
                smm[r0 + 8] = mrow[mt][1];  sml[r0 + 8] = lrow2[mt][1];
            }
#pragma unroll
            for (int n8 = 0; n8 < 8; n8++) {
                *(float2*)&smf[r0 * 66 + n8 * 8 + 2 * tq] =
                    make_float2(oa[mt][n8].x, oa[mt][n8].y);
                *(float2*)&smf[(r0 + 8) * 66 + n8 * 8 + 2 * tq] =
                    make_float2(oa[mt][n8].z, oa[mt][n8].w);
            }
        }
    }
    __syncthreads();
    if (jj == 0) {
        const int b = bh >> 3, h_ = bh & 7;
#pragma unroll
        for (int mt = 0; mt < 2; mt++) {
#pragma unroll
            for (int hh = 0; hh < 2; hh++) {
                const int r = rb + mt * 16 + g + 8 * hh;
                const float m1 = smm[r], l1 = sml[r];
                const float m0v = mrow[mt][hh], l0v = lrow2[mt][hh];
                const float mm = fmaxf(m0v, m1);
                const float c0 = ex2(SCALE * (m0v - mm));
                const float c1 = ex2(SCALE * (m1 - mm));
                const float inv = 1.0f / (l0v * c0 + l1 * c1);
                const size_t ub =
                    ((size_t)b * NSP + ntile + r) * 256 + h_ * 32;
#pragma unroll
                for (int n8 = 0; n8 < 8; n8++) {
                    const float2 o1 = *(float2*)&smf[r * 66 + n8 * 8 + 2 * tq];
                    const float fx = hh ? oa[mt][n8].z : oa[mt][n8].x;
                    const float fy = hh ? oa[mt][n8].w : oa[mt][n8].y;
                    g_oh[ub + n8 * 4 + tq] =
                        h2pk((fx * c0 + o1.x * c1) * inv,
                             (fy * c0 + o1.y * c1) * inv);
                }
            }
        }
    }
}

// ---------------------------------------------------------------------------
extern "C" void kernel_launch(void* const* d_in, const int* in_sizes, int n_in,
                              void* d_out, int out_size) {
    const float* x      = (const float*)d_in[0];
    const float* w_qkv  = (const float*)d_in[1];
    const float* w_proj = (const float*)d_in[2];
    float* out = (float*)d_out;

    cudaFuncSetAttribute(hgemm_kernel<0>,
                         cudaFuncAttributeMaxDynamicSharedMemorySize, GEMM_SMEM);
    cudaFuncSetAttribute(hgemm_kernel<1>,
                         cudaFuncAttributeMaxDynamicSharedMemorySize, GEMM_SMEM);
    cudaFuncSetAttribute(attn_kernel,
                         cudaFuncAttributeMaxDynamicSharedMemorySize, ATTN_SMEM);

    f2h_kernel<<<1536, 256>>>(w_qkv, 0);
    f2h_kernel<<<512, 256>>>(w_proj, 1);
    convx_kernel<<<dim3(128, 16, 4), 256>>>(x);
    rope_tab_kernel<<<4, 256>>>();
    hgemm_kernel<0><<<dim3(32, 12, NB), 256, GEMM_SMEM>>>(nullptr);
    attn_kernel<<<dim3(32, 32), 256, ATTN_SMEM>>>();
    hgemm_kernel<1><<<dim3(32, 4, NB), 256, GEMM_SMEM>>>(out);
}

// round 13
// speedup vs baseline: 9.1427x; 1.0366x over previous
#include <cuda_runtime.h>
#include <cuda_fp16.h>

#define NB    4
#define CDIM  512
#define NHEAD 8
#define HD    64
#define NSP   4096
#define NBH   32

typedef unsigned long long ull;

// fp16 storage, addressed as uint = half2 pair (low = even index)
__device__ unsigned g_xh[NB * NSP * 256];    // x^T  [b][n][c/2]
__device__ unsigned g_wh[1536 * 256];        // w_qkv [o][c/2]
__device__ unsigned g_wph[512 * 256];        // w_proj [o][c/2]
__device__ unsigned g_qh[NBH * NSP * 32];    // [bh][n][d/2]  (roped)
__device__ unsigned g_kh[NBH * NSP * 32];
__device__ unsigned g_vt[NBH * HD * 2048];   // V^T [bh][d][n/2]
__device__ unsigned g_oh[NB * NSP * 256];    // attn out [b][n][c/2]
__device__ float2  g_rt[64 * 16];            // rope table [pos][freq] (cos,sin)

// ---- helpers ----
__device__ __forceinline__ unsigned h2pk(float lo, float hi) {
    unsigned r; asm("cvt.rn.f16x2.f32 %0,%1,%2;" : "=r"(r) : "f"(hi), "f"(lo)); return r;
}
__device__ __forceinline__ float ex2(float x) {
    float r; asm("ex2.approx.f32 %0,%1;" : "=f"(r) : "f"(x)); return r;
}
__device__ __forceinline__ unsigned hex2(unsigned a) {
    unsigned r; asm("ex2.approx.f16x2 %0,%1;" : "=r"(r) : "r"(a)); return r;
}
__device__ __forceinline__ ull pk2(float lo, float hi) {
    ull r; asm("mov.b64 %0,{%1,%2};" : "=l"(r) : "f"(lo), "f"(hi)); return r;
}
__device__ __forceinline__ void upk2(ull v, float& lo, float& hi) {
    asm("mov.b64 {%0,%1},%2;" : "=f"(lo), "=f"(hi) : "l"(v));
}
__device__ __forceinline__ ull ffma2(ull a, ull b, ull c) {
    ull r; asm("fma.rn.f32x2 %0,%1,%2,%3;" : "=l"(r) : "l"(a), "l"(b), "l"(c)); return r;
}
__device__ __forceinline__ ull fmul2(ull a, ull b) {
    ull r; asm("mul.rn.f32x2 %0,%1,%2;" : "=l"(r) : "l"(a), "l"(b)); return r;
}
__device__ __forceinline__ void mma16(float4& d, unsigned a0, unsigned a1,
                                      unsigned a2, unsigned a3,
                                      unsigned b0, unsigned b1) {
    asm("mma.sync.aligned.m16n8k16.row.col.f32.f16.f16.f32 "
        "{%0,%1,%2,%3},{%4,%5,%6,%7},{%8,%9},{%0,%1,%2,%3};"
        : "+f"(d.x), "+f"(d.y), "+f"(d.z), "+f"(d.w)
        : "r"(a0), "r"(a1), "r"(a2), "r"(a3), "r"(b0), "r"(b1));
}
__device__ __forceinline__ void ldsm4(uint4& v, unsigned a) {
    asm volatile("ldmatrix.sync.aligned.m8n8.x4.shared.b16 {%0,%1,%2,%3},[%4];"
                 : "=r"(v.x), "=r"(v.y), "=r"(v.z), "=r"(v.w) : "r"(a));
}
__device__ __forceinline__ void cpa16(unsigned dst, const void* src) {
    asm volatile("cp.async.cg.shared.global [%0], [%1], 16;"
                 :: "r"(dst), "l"(src) : "memory");
}
#define CP_COMMIT() asm volatile("cp.async.commit_group;" ::: "memory")
#define CP_WAIT1()  asm volatile("cp.async.wait_group 1;" ::: "memory")

// ---------------------------------------------------------------------------
// Prep: weights fp32->fp16 + rope table, one kernel.
// blocks [0,1536): w_qkv; [1536,2048): w_proj; 2048: rope table.
// ---------------------------------------------------------------------------
__global__ void __launch_bounds__(256) prep_kernel(const float* __restrict__ wqkv,
                                                   const float* __restrict__ wproj) {
    const int blk = blockIdx.x;
    if (blk < 2048) {
        const float* src = (blk < 1536) ? wqkv : wproj;
        unsigned* dst = (blk < 1536) ? g_wh : g_wph;
        const int i = ((blk < 1536) ? blk : blk - 1536) * 256 + threadIdx.x;
        float2 v = ((const float2*)src)[i];
        dst[i] = h2pk(v.x, v.y);
    } else {
#pragma unroll
        for (int q = 0; q < 4; q++) {
            const int idx = threadIdx.x * 4 + q;   // [pos][f]
            const int f = idx & 15, pos = idx >> 4;
            const float ang = (float)pos * exp2f(-0.8304820237218406f * (float)f);
            float sn, cs;
            sincosf(ang, &sn, &cs);
            g_rt[idx] = make_float2(cs, sn);
        }
    }
}

__global__ void __launch_bounds__(256) convx_kernel(const float* __restrict__ x) {
    __shared__ float ts[32][33];
    const int t = threadIdx.x;
    const int n0 = blockIdx.x * 32, c0 = blockIdx.y * 32, b = blockIdx.z;
    const int tx = t & 31, ty = t >> 5;
    const float* xp = x + ((size_t)b * CDIM + c0) * NSP + n0;
#pragma unroll
    for (int i = 0; i < 4; i++)
        ts[ty + 8 * i][tx] = xp[(size_t)(ty + 8 * i) * NSP + tx];
    __syncthreads();
    const int r = t >> 4, cp = t & 15;
#pragma unroll
    for (int i = 0; i < 2; i++) {
        const int rr = r + 16 * i;
        g_xh[((size_t)b * NSP + n0 + rr) * 256 + (c0 >> 1) + cp] =
            h2pk(ts[2 * cp][rr], ts[2 * cp + 1][rr]);
    }
}

// ---------------------------------------------------------------------------
// fp16 tensor GEMM, 128x128 tile, KT=64, cp.async double buffer, ldmatrix.
// MODE 0:
//   by<8  (q,k): A = tokens, B = w; epilogue stages [n][o] in smem, applies
//                RoPE from g_rt, writes fp16 [bh][n][d].
//   by>=8 (v):   A = w, B = tokens; frags hold adjacent n -> direct V^T store.
// MODE 1: A = w_proj, B = g_oh; out f32 [b][o][n].
// ---------------------------------------------------------------------------
#define GEMM_SMEM (2 * 9216 * 4)

template <int MODE>
__global__ void __launch_bounds__(256, 2) hgemm_kernel(float* __restrict__ Out) {
    extern __shared__ unsigned sm[];
    const unsigned smb = (unsigned)__cvta_generic_to_shared(sm);

    const int t    = threadIdx.x;
    const int lane = t & 31;
    const int g    = lane >> 2;
    const int tq   = lane & 3;
    const int w    = t >> 5;
    const int wr   = (w >> 2) * 64;
    const int wn   = (w & 3) * 32;
    const bool vblk = (MODE == 0) && (blockIdx.y >= 8);

    const unsigned* Ag;
    const unsigned* Bg;
    if (MODE == 0) {
        const unsigned* tok = g_xh + ((size_t)blockIdx.z * NSP + blockIdx.x * 128) * 256;
        const unsigned* wgt = g_wh + (size_t)blockIdx.y * 128 * 256;
        Ag = vblk ? wgt : tok;
        Bg = vblk ? tok : wgt;
    } else {
        Ag = g_wph + (size_t)blockIdx.y * 128 * 256;
        Bg = g_oh + ((size_t)blockIdx.z * NSP + blockIdx.x * 128) * 256;
    }

    const int fr = t >> 3, fc = (t & 7) * 4;
    const int lrow = lane & 15;
    const int lcolb = (lane >> 4) * 16;
    const unsigned ab = smb + (wr + lrow) * 144 + lcolb;
    const unsigned bb = smb + 18432 + (wn + lrow) * 144 + lcolb;

    float4 acc[4][4];
#pragma unroll
    for (int i = 0; i < 4; i++)
#pragma unroll
        for (int j = 0; j < 4; j++) acc[i][j] = make_float4(0.f, 0.f, 0.f, 0.f);

#define FILL(st, kt)                                                          \
    {                                                                         \
        _Pragma("unroll")                                                     \
        for (int i = 0; i < 4; i++) {                                         \
            const int r = fr + 32 * i;                                        \
            cpa16(smb + ((st) * 9216 + r * 36 + fc) * 4,                      \
                  Ag + (size_t)r * 256 + (kt) * 32 + fc);                     \
            cpa16(smb + ((st) * 9216 + 4608 + r * 36 + fc) * 4,               \
                  Bg + (size_t)r * 256 + (kt) * 32 + fc);                     \
        }                                                                     \
    }

    FILL(0, 0); CP_COMMIT();
    FILL(1, 1); CP_COMMIT();

    for (int kt = 0; kt < 8; kt++) {
        CP_WAIT1();
        __syncthreads();
        const unsigned stoff = (kt & 1) * 36864;
#pragma unroll
        for (int k16 = 0; k16 < 4; k16++) {
            uint4 av[4], bv[2];
#pragma unroll
            for (int mt = 0; mt < 4; mt++)
                ldsm4(av[mt], ab + stoff + mt * 2304 + k16 * 32);
#pragma unroll
            for (int p = 0; p < 2; p++)
                ldsm4(bv[p], bb + stoff + p * 2304 + k16 * 32);
#pragma unroll
            for (int mt = 0; mt < 4; mt++)
#pragma unroll
                for (int nt = 0; nt < 4; nt++) {
                    const uint4& b4 = bv[nt >> 1];
                    const unsigned b0 = (nt & 1) ? b4.y : b4.x;
                    const unsigned b1 = (nt & 1) ? b4.w : b4.z;
                    mma16(acc[mt][nt], av[mt].x, av[mt].y, av[mt].z, av[mt].w,
                          b0, b1);
                }
        }
        __syncthreads();
        if (kt + 2 < 8) FILL(kt & 1, kt + 2);
        CP_COMMIT();
    }
#undef FILL

    // ---- epilogues ----
    if (MODE == 1) {
#pragma unroll
        for (int mt = 0; mt < 4; mt++)
#pragma unroll
            for (int nt = 0; nt < 4; nt++) {
                const float4 c = acc[mt][nt];
                const int o = blockIdx.y * 128 + wr + mt * 16 + g;
                const int n = blockIdx.x * 128 + wn + nt * 8 + 2 * tq;
                const size_t base = ((size_t)blockIdx.z * CDIM + o) * NSP + n;
                *(float2*)&Out[base]           = make_float2(c.x, c.y);
                *(float2*)&Out[base + 8 * NSP] = make_float2(c.z, c.w);
            }
        return;
    }

    if (vblk) {
        const int hv = (blockIdx.y & 3) << 1;
#pragma unroll
        for (int mt = 0; mt < 4; mt++)
#pragma unroll
            for (int nt = 0; nt < 4; nt++) {
                const float4 c = acc[mt][nt];
                const int ol = wr + mt * 16 + g;
                const int h  = hv + (ol >> 6);
                const int d  = ol & 63;
                const int nn = blockIdx.x * 128 + wn + nt * 8 + 2 * tq;
                const size_t base =
                    ((size_t)(blockIdx.z * NHEAD + h) * HD + d) * 2048 + (nn >> 1);
                g_vt[base]            = h2pk(c.x, c.y);
                g_vt[base + 8 * 2048] = h2pk(c.z, c.w);   // d+8
            }
        return;
    }

    // q/k: stage fp32 tile [n][o] (stride 132), then RoPE + fp16 store
    float* smf = (float*)sm;
#pragma unroll
    for (int mt = 0; mt < 4; mt++)
#pragma unroll
        for (int nt = 0; nt < 4; nt++) {
            const float4 c = acc[mt][nt];
            const int n  = wr + mt * 16 + g;
            const int ol = wn + nt * 8 + 2 * tq;
            smf[n * 132 + ol]           = c.x;
            smf[n * 132 + ol + 1]       = c.y;
            smf[(n + 8) * 132 + ol]     = c.z;
            smf[(n + 8) * 132 + ol + 1] = c.w;
        }
    __syncthreads();

    {
        unsigned* dst = (blockIdx.y >> 2) ? g_kh : g_qh;
        const int dp = t & 15, hp = (t >> 4) & 1, nw = t >> 5;
        const int h  = ((blockIdx.y & 3) << 1) + hp;
        const int f0 = (dp < 8) ? 2 * dp : 2 * dp - 16;
        const size_t bhb = (size_t)(blockIdx.z * NHEAD + h) * NSP;
#pragma unroll
        for (int i = 0; i < 16; i++) {
            const int n  = nw * 16 + i;
            const int gn = blockIdx.x * 128 + n;
            const int pos = (dp < 8) ? (gn >> 6) : (gn & 63);
            const float2 cs0 = g_rt[pos * 16 + f0];
            const float2 cs1 = g_rt[pos * 16 + f0 + 1];
            const float* row = smf + n * 132 + hp * 64;
            const float a1 = row[2 * dp],      a2 = row[2 * dp + 1];
            const float b1 = row[2 * dp + 32], b2 = row[2 * dp + 33];
            const size_t ub = (bhb + gn) * 32;
            dst[ub + dp]      = h2pk(a1 * cs0.x - b1 * cs0.y,
                                     a2 * cs1.x - b2 * cs1.y);
            dst[ub + 16 + dp] = h2pk(a1 * cs0.y + b1 * cs0.x,
                                     a2 * cs1.y + b2 * cs1.x);
        }
    }
}

// ---------------------------------------------------------------------------
// Flash attention, split-c, ldmatrix, f16x2 exp, ones-column l accumulator.
// BR=128, BC=128, 8 warps: warp w -> row strip (w>>1)*32, column half w&1.
// Smem (uints): Qs 128x36 @0, K[2] 128x36 @4608+st*4608, Vt[2] 64x68 @13824+st*4352.
// ---------------------------------------------------------------------------
#define ATTN_SMEM (22528 * 4)
#define SCALE 0.18033688011112042f   // hd^-1/2 * log2(e)
#define ONES_H2 0x3C003C00u

__global__ void __launch_bounds__(256, 1) attn_kernel() {
    extern __shared__ unsigned smu[];
    unsigned* Qs = smu;
    const unsigned smb = (unsigned)__cvta_generic_to_shared(smu);

    const int t    = threadIdx.x;
    const int lane = t & 31;
    const int g    = lane >> 2;
    const int tq   = lane & 3;
    const int w    = t >> 5;
    const int rb   = (w >> 1) * 32;
    const int jj   = w & 1;
    const int bh   = blockIdx.y;
    const int ntile = blockIdx.x * 128;

    const unsigned* Qg  = g_qh + ((size_t)bh * NSP + ntile) * 32;
    const unsigned* Kg  = g_kh + (size_t)bh * NSP * 32;
    const unsigned* Vtg = g_vt + (size_t)bh * HD * 2048;

    const int lrow = lane & 15;
    const int lcolb = (lane >> 4) * 16;
    const unsigned qa = smb + (rb + lrow) * 144 + lcolb;
    const unsigned ka = smb + (64 * jj + lrow) * 144 + lcolb;
    const unsigned va = smb + lrow * 272 + jj * 128 + lcolb;

    // Q fill
    {
        const int r = t >> 1, sg = (t & 1) * 16;
        const uint4* src = (const uint4*)(Qg + (size_t)r * 32 + sg);
        uint4* dst = (uint4*)(Qs + r * 36 + sg);
        dst[0] = src[0]; dst[1] = src[1]; dst[2] = src[2]; dst[3] = src[3];
    }

#define AFILL(kt, st)                                                         \
    {                                                                         \
        _Pragma("unroll")                                                     \
        for (int i = 0; i < 4; i++) {                                         \
            const int id = t + 256 * i;                                       \
            const int r = id >> 3, ch = (id & 7) * 4;                         \
            cpa16(smb + (4608 + (st) * 4608 + r * 36 + ch) * 4,               \
                  Kg + (size_t)((kt) * 128 + r) * 32 + ch);                   \
        }                                                                     \
        _Pragma("unroll")                                                     \
        for (int i = 0; i < 4; i++) {                                         \
            const int id = t + 256 * i;                                       \
            const int d = id >> 4, ch = (id & 15) * 4;                        \
            cpa16(smb + (13824 + (st) * 4352 + d * 68 + ch) * 4,              \
                  Vtg + (size_t)d * 2048 + (kt) * 64 + ch);                   \
        }                                                                     \
    }

    AFILL(0, 0); CP_COMMIT();
    AFILL(1, 1); CP_COMMIT();

    float4 oa[2][8];
    float4 la[2];    // ones-column accumulators: la[mt].x = l(row), .z = l(row+8)
#pragma unroll
    for (int mt = 0; mt < 2; mt++) {
#pragma unroll
        for (int n8 = 0; n8 < 8; n8++) oa[mt][n8] = make_float4(0.f, 0.f, 0.f, 0.f);
        la[mt] = make_float4(0.f, 0.f, 0.f, 0.f);
    }
    float mrow[2][2];
#pragma unroll
    for (int mt = 0; mt < 2; mt++) { mrow[mt][0] = -1e30f; mrow[mt][1] = -1e30f; }

    const ull sc2 = pk2(SCALE, SCALE);

    for (int kt = 0; kt < 32; kt++) {
        CP_WAIT1();
        __syncthreads();
        const unsigned kbase = ka + 18432 + (kt & 1) * 18432;
        const unsigned vbase = va + 55296 + (kt & 1) * 17408;

        // ---- S = Q K^T ----
        float4 sa[2][8];
#pragma unroll
        for (int mt = 0; mt < 2; mt++)
#pragma unroll
            for (int n8 = 0; n8 < 8; n8++) sa[mt][n8] = make_float4(0.f, 0.f, 0.f, 0.f);
#pragma unroll
        for (int k16 = 0; k16 < 4; k16++) {
            uint4 a0v, a1v, bk[4];
            ldsm4(a0v, qa + k16 * 32);
            ldsm4(a1v, qa + 2304 + k16 * 32);
#pragma unroll
            for (int p = 0; p < 4; p++)
                ldsm4(bk[p], kbase + p * 2304 + k16 * 32);
#pragma unroll
            for (int p = 0; p < 4; p++) {
                mma16(sa[0][2 * p],     a0v.x, a0v.y, a0v.z, a0v.w, bk[p].x, bk[p].z);
                mma16(sa[0][2 * p + 1], a0v.x, a0v.y, a0v.z, a0v.w, bk[p].y, bk[p].w);
                mma16(sa[1][2 * p],     a1v.x, a1v.y, a1v.z, a1v.w, bk[p].x, bk[p].z);
                mma16(sa[1][2 * p + 1], a1v.x, a1v.y, a1v.z, a1v.w, bk[p].y, bk[p].w);
            }
        }

        // ---- online softmax: f16x2 exp, packed f32x2 bias/corrections ----
        unsigned pa[2][8], pb[2][8];
#pragma unroll
        for (int mt = 0; mt < 2; mt++) {
            float nm0 = -1e30f, nm1 = -1e30f;
#pragma unroll
            for (int n8 = 0; n8 < 8; n8++) {
                nm0 = fmaxf(nm0, fmaxf(sa[mt][n8].x, sa[mt][n8].y));
                nm1 = fmaxf(nm1, fmaxf(sa[mt][n8].z, sa[mt][n8].w));
            }
            nm0 = fmaxf(nm0, __shfl_xor_sync(0xffffffffu, nm0, 1));
            nm0 = fmaxf(nm0, __shfl_xor_sync(0xffffffffu, nm0, 2));
            nm1 = fmaxf(nm1, __shfl_xor_sync(0xffffffffu, nm1, 1));
            nm1 = fmaxf(nm1, __shfl_xor_sync(0xffffffffu, nm1, 2));
            const float mn0 = fmaxf(mrow[mt][0], nm0);
            const float mn1 = fmaxf(mrow[mt][1], nm1);
            const float cr0 = ex2(SCALE * (mrow[mt][0] - mn0));
            const float cr1 = ex2(SCALE * (mrow[mt][1] - mn1));
            mrow[mt][0] = mn0; mrow[mt][1] = mn1;
            const ull nb02 = pk2(-SCALE * mn0, -SCALE * mn0);
            const ull nb12 = pk2(-SCALE * mn1, -SCALE * mn1);
#pragma unroll
            for (int n8 = 0; n8 < 8; n8++) {
                ull exy = ffma2(*(const ull*)&sa[mt][n8].x, sc2, nb02);
                ull ezw = ffma2(*(const ull*)&sa[mt][n8].z, sc2, nb12);
                float ax, ay, az, aw;
                upk2(exy, ax, ay);
                upk2(ezw, az, aw);
                pa[mt][n8] = hex2(h2pk(ax, ay));
                pb[mt][n8] = hex2(h2pk(az, aw));
            }
            const ull c02 = pk2(cr0, cr0), c12 = pk2(cr1, cr1);
#pragma unroll
            for (int n8 = 0; n8 < 8; n8++) {
                ull* ox = (ull*)&oa[mt][n8].x;
                ull* oz = (ull*)&oa[mt][n8].z;
                *ox = fmul2(*ox, c02);
                *oz = fmul2(*oz, c12);
            }
            ull* lx = (ull*)&la[mt].x;
            ull* lz = (ull*)&la[mt].z;
            *lx = fmul2(*lx, c02);
            *lz = fmul2(*lz, c12);
        }

        // ---- O += P V, l += P 1 ----
#pragma unroll
        for (int kc = 0; kc < 4; kc++) {
            uint4 bv[4];
#pragma unroll
            for (int p = 0; p < 4; p++)
                ldsm4(bv[p], vbase + p * 4352 + kc * 32);
#pragma unroll
            for (int p = 0; p < 4; p++) {
                mma16(oa[0][2 * p],     pa[0][2 * kc], pb[0][2 * kc],
                      pa[0][2 * kc + 1], pb[0][2 * kc + 1], bv[p].x, bv[p].z);
                mma16(oa[0][2 * p + 1], pa[0][2 * kc], pb[0][2 * kc],
                      pa[0][2 * kc + 1], pb[0][2 * kc + 1], bv[p].y, bv[p].w);
                mma16(oa[1][2 * p],     pa[1][2 * kc], pb[1][2 * kc],
                      pa[1][2 * kc + 1], pb[1][2 * kc + 1], bv[p].x, bv[p].z);
                mma16(oa[1][2 * p + 1], pa[1][2 * kc], pb[1][2 * kc],
                      pa[1][2 * kc + 1], pb[1][2 * kc + 1], bv[p].y, bv[p].w);
            }
            mma16(la[0], pa[0][2 * kc], pb[0][2 * kc],
                  pa[0][2 * kc + 1], pb[0][2 * kc + 1], ONES_H2, ONES_H2);
            mma16(la[1], pa[1][2 * kc], pb[1][2 * kc],
                  pa[1][2 * kc + 1], pb[1][2 * kc + 1], ONES_H2, ONES_H2);
        }

        __syncthreads();
        if (kt + 2 < 32) AFILL(kt + 2, kt & 1);
        CP_COMMIT();
    }
#undef AFILL

    // ---- merge halves: jj=1 publishes, jj=0 combines & stores ----
    __syncthreads();
    float* smf  = (float*)smu;          // O1: 128 x 66
    float* smm  = smf + 8448;
    float* sml  = smf + 8576;

    if (jj == 1) {
#pragma unroll
        for (int mt = 0; mt < 2; mt++) {
            const int r0 = rb + mt * 16 + g;
            if (tq == 0) {
                smm[r0]     = mrow[mt][0];  sml[r0]     = la[mt].x;
                smm[r0 + 8] = mrow[mt][1];  sml[r0 + 8] = la[mt].z;
            }
#pragma unroll
            for (int n8 = 0; n8 < 8; n8++) {
                *(float2*)&smf[r0 * 66 + n8 * 8 + 2 * tq] =
                    make_float2(oa[mt][n8].x, oa[mt][n8].y);
                *(float2*)&smf[(r0 + 8) * 66 + n8 * 8 + 2 * tq] =
                    make_float2(oa[mt][n8].z, oa[mt][n8].w);
            }
        }
    }
    __syncthreads();
    if (jj == 0) {
        const int b = bh >> 3, h_ = bh & 7;
#pragma unroll
        for (int mt = 0; mt < 2; mt++) {
#pragma unroll
            for (int hh = 0; hh < 2; hh++) {
                const int r = rb + mt * 16 + g + 8 * hh;
                const float m1 = smm[r], l1 = sml[r];
                const float m0v = mrow[mt][hh];
                const float l0v = hh ? la[mt].z : la[mt].x;
                const float mm = fmaxf(m0v, m1);
                const float c0 = ex2(SCALE * (m0v - mm));
                const float c1 = ex2(SCALE * (m1 - mm));
                const float inv = 1.0f / (l0v * c0 + l1 * c1);
                const size_t ub =
                    ((size_t)b * NSP + ntile + r) * 256 + h_ * 32;
#pragma unroll
                for (int n8 = 0; n8 < 8; n8++) {
                    const float2 o1 = *(float2*)&smf[r * 66 + n8 * 8 + 2 * tq];
                    const float fx = hh ? oa[mt][n8].z : oa[mt][n8].x;
                    const float fy = hh ? oa[mt][n8].w : oa[mt][n8].y;
                    g_oh[ub + n8 * 4 + tq] =
                        h2pk((fx * c0 + o1.x * c1) * inv,
                             (fy * c0 + o1.y * c1) * inv);
                }
            }
        }
    }
}

// ---------------------------------------------------------------------------
extern "C" void kernel_launch(void* const* d_in, const int* in_sizes, int n_in,
                              void* d_out, int out_size) {
    const float* x      = (const float*)d_in[0];
    const float* w_qkv  = (const float*)d_in[1];
    const float* w_proj = (const float*)d_in[2];
    float* out = (float*)d_out;

    cudaFuncSetAttribute(hgemm_kernel<0>,
                         cudaFuncAttributeMaxDynamicSharedMemorySize, GEMM_SMEM);
    cudaFuncSetAttribute(hgemm_kernel<1>,
                         cudaFuncAttributeMaxDynamicSharedMemorySize, GEMM_SMEM);
    cudaFuncSetAttribute(attn_kernel,
                         cudaFuncAttributeMaxDynamicSharedMemorySize, ATTN_SMEM);

    prep_kernel<<<2049, 256>>>(w_qkv, w_proj);
    convx_kernel<<<dim3(128, 16, 4), 256>>>(x);
    hgemm_kernel<0><<<dim3(32, 12, NB), 256, GEMM_SMEM>>>(nullptr);
    attn_kernel<<<dim3(32, 32), 256, ATTN_SMEM>>>();
    hgemm_kernel<1><<<dim3(32, 4, NB), 256, GEMM_SMEM>>>(out);
}